// round 13
// baseline (speedup 1.0000x reference)
#include <cuda_runtime.h>
#include <cuda_fp16.h>
#include <math.h>

// Problem constants
#define BATCH 4
#define LQQ   2048
#define LKK   2048
#define DMODEL 1024
#define NHEAD 16
#define DHEAD 64

// Scratch (static device arrays -- no runtime allocation allowed)
__device__ __half g_qln [BATCH * LQQ * DMODEL];
__device__ __half g_kvln[BATCH * LKK * DMODEL];
__device__ __half g_q   [BATCH * LQQ * DMODEL];
__device__ __half g_k   [BATCH * LKK * DMODEL];
__device__ __half g_vt  [BATCH * NHEAD * DHEAD * LKK];  // [b][h][d][kv]
__device__ __half g_ao  [BATCH * LQQ * DMODEL];
__device__ __half g_wq  [DMODEL * DMODEL];  // transposed [N][K]
__device__ __half g_wk  [DMODEL * DMODEL];
__device__ __half g_wv  [DMODEL * DMODEL];
__device__ __half g_wo  [DMODEL * DMODEL];
__device__ float  g_maskf[BATCH * LKK];   // 0.0 = masked, 1.0 = keep
__device__ int    g_mask_mode;            // 0=uint8, 1=int32, 2=float32

// ---------------------------------------------------------------------------
// mma / cp.async / ldmatrix helpers
// ---------------------------------------------------------------------------
__device__ __forceinline__ void mma_f16(float c[4],
                                        unsigned a0, unsigned a1, unsigned a2, unsigned a3,
                                        unsigned b0, unsigned b1) {
    asm volatile(
        "mma.sync.aligned.m16n8k16.row.col.f32.f16.f16.f32 "
        "{%0,%1,%2,%3},{%4,%5,%6,%7},{%8,%9},{%0,%1,%2,%3};"
        : "+f"(c[0]), "+f"(c[1]), "+f"(c[2]), "+f"(c[3])
        : "r"(a0), "r"(a1), "r"(a2), "r"(a3), "r"(b0), "r"(b1));
}

__device__ __forceinline__ void cp_async16(void* smem_dst, const void* gmem_src) {
    unsigned sa = (unsigned)__cvta_generic_to_shared(smem_dst);
    asm volatile("cp.async.cg.shared.global [%0], [%1], 16;" :: "r"(sa), "l"(gmem_src));
}
__device__ __forceinline__ void cp_commit() {
    asm volatile("cp.async.commit_group;");
}
template <int N>
__device__ __forceinline__ void cp_wait() {
    asm volatile("cp.async.wait_group %0;" :: "n"(N));
}

__device__ __forceinline__ unsigned smem_u32(const void* p) {
    return (unsigned)__cvta_generic_to_shared(p);
}
__device__ __forceinline__ void ldsm4(unsigned& d0, unsigned& d1,
                                      unsigned& d2, unsigned& d3, unsigned saddr) {
    asm volatile("ldmatrix.sync.aligned.m8n8.x4.shared.b16 {%0,%1,%2,%3}, [%4];"
                 : "=r"(d0), "=r"(d1), "=r"(d2), "=r"(d3) : "r"(saddr));
}
__device__ __forceinline__ unsigned packh2(float a, float b) {
    __half2 h = __floats2half2_rn(a, b);
    return *(unsigned*)&h;
}

// ---------------------------------------------------------------------------
// Mask dtype detection (bool array may arrive as u8/i32/f32)
// ---------------------------------------------------------------------------
__global__ void detect_mask_kernel(const unsigned char* __restrict__ m) {
    __shared__ int nz[4];
    if (threadIdx.x < 4) nz[threadIdx.x] = 0;
    __syncthreads();
    int loc = 0;
    for (int i = threadIdx.x; i < 8192; i += blockDim.x)
        if (m[i]) loc = 1;
    if (loc) atomicOr(&nz[threadIdx.x & 3], 1);
    __syncthreads();
    if (threadIdx.x == 0) {
        int mode;
        int tot = nz[0] | nz[1] | nz[2] | nz[3];
        if (!tot)                          mode = 0;
        else if (!(nz[1] | nz[2] | nz[3])) mode = 1; // int32 LE
        else if (!(nz[0] | nz[1]))         mode = 2; // float32 (0x3F800000)
        else                               mode = 0; // uint8/bool
        g_mask_mode = mode;
    }
}

// Convert mask (any dtype) into multiplicative float mask: 0 = masked, 1 = keep
__global__ void maskf_kernel(const void* __restrict__ m) {
    int i = blockIdx.x * blockDim.x + threadIdx.x;
    if (i >= BATCH * LKK) return;
    int mode = g_mask_mode;
    bool mm = (mode == 0) ? (((const unsigned char*)m)[i] != 0)
            : (mode == 1) ? (((const int*)m)[i] != 0)
                          : (((const float*)m)[i] != 0.f);
    g_maskf[i] = mm ? 0.f : 1.f;
}

// ---------------------------------------------------------------------------
// Fused weight transpose + fp16 convert for all 4 weights.
// blockIdx.z selects the (W, WT) pair. W[K][N] f32 -> WT[N][K] half.
// ---------------------------------------------------------------------------
__global__ void wtrans4_kernel(const float* __restrict__ W0, __half* __restrict__ T0,
                               const float* __restrict__ W1, __half* __restrict__ T1,
                               const float* __restrict__ W2, __half* __restrict__ T2,
                               const float* __restrict__ W3, __half* __restrict__ T3) {
    const float* W = (blockIdx.z == 0) ? W0 : (blockIdx.z == 1) ? W1
                   : (blockIdx.z == 2) ? W2 : W3;
    __half* WT     = (blockIdx.z == 0) ? T0 : (blockIdx.z == 1) ? T1
                   : (blockIdx.z == 2) ? T2 : T3;
    __shared__ float t[32][33];
    int n0 = blockIdx.x * 32, k0 = blockIdx.y * 32;
    #pragma unroll
    for (int i = 0; i < 4; i++) {
        int k = threadIdx.y + i * 8;
        t[k][threadIdx.x] = W[(size_t)(k0 + k) * DMODEL + n0 + threadIdx.x];
    }
    __syncthreads();
    #pragma unroll
    for (int i = 0; i < 4; i++) {
        int n = threadIdx.y + i * 8;
        WT[(size_t)(n0 + n) * DMODEL + k0 + threadIdx.x] = __float2half(t[threadIdx.x][n]);
    }
}

// ---------------------------------------------------------------------------
// Fused LayerNorm for x and context: one block per row; rows [0, B*LQ) are x,
// rows [B*LQ, B*LQ+B*LK) are context. Output fp16.
// ---------------------------------------------------------------------------
__global__ void ln2_kernel(const float* __restrict__ x,
                           const float* __restrict__ ctx,
                           const float* __restrict__ wq_, const float* __restrict__ bq_,
                           const float* __restrict__ wc_, const float* __restrict__ bc_,
                           __half* __restrict__ oq_, __half* __restrict__ oc_) {
    int row = blockIdx.x;
    bool isq = row < BATCH * LQQ;
    const float* src = isq ? x : ctx;
    const float* w   = isq ? wq_ : wc_;
    const float* bia = isq ? bq_ : bc_;
    __half* out      = isq ? oq_ : oc_;
    int r = isq ? row : row - BATCH * LQQ;

    int tid = threadIdx.x;
    const float4* xr = reinterpret_cast<const float4*>(src + (size_t)r * DMODEL);
    float4 a = xr[tid];
    float s  = a.x + a.y + a.z + a.w;
    float ss = a.x * a.x + a.y * a.y + a.z * a.z + a.w * a.w;

    __shared__ float rs[8], rss[8], stats[2];
    #pragma unroll
    for (int o = 16; o; o >>= 1) {
        s  += __shfl_xor_sync(0xffffffffu, s,  o);
        ss += __shfl_xor_sync(0xffffffffu, ss, o);
    }
    int wid = tid >> 5, lane = tid & 31;
    if (!lane) { rs[wid] = s; rss[wid] = ss; }
    __syncthreads();
    if (tid == 0) {
        float S = 0.f, SS = 0.f;
        #pragma unroll
        for (int i = 0; i < 8; i++) { S += rs[i]; SS += rss[i]; }
        float mean = S * (1.0f / DMODEL);
        float var  = SS * (1.0f / DMODEL) - mean * mean;
        stats[0] = mean;
        stats[1] = rsqrtf(var + 1e-5f);
    }
    __syncthreads();
    float mean = stats[0], rstd = stats[1];
    float4 wv = reinterpret_cast<const float4*>(w)[tid];
    float4 bv = reinterpret_cast<const float4*>(bia)[tid];
    __half2 h0 = __floats2half2_rn((a.x - mean) * rstd * wv.x + bv.x,
                                   (a.y - mean) * rstd * wv.y + bv.y);
    __half2 h1 = __floats2half2_rn((a.z - mean) * rstd * wv.z + bv.z,
                                   (a.w - mean) * rstd * wv.w + bv.w);
    __half2* orow = reinterpret_cast<__half2*>(out + (size_t)r * DMODEL);
    orow[tid * 2]     = h0;
    orow[tid * 2 + 1] = h1;
}

// ---------------------------------------------------------------------------
// fp16 tensor-core GEMM core, cp.async 3-stage pipeline, ldmatrix loads.
// C[M,N] = A[M,K] @ BT[N,K]^T. 128x128x32 tiles, 256 threads, warp 64x32.
// mode: 0 = half out, 1 = half transposed-per-head out (g_vt), 2 = float out.
// ---------------------------------------------------------------------------
#define TBM 128
#define TBN 128
#define TBK 32
#define KPAD 40                 // halves per smem row
#define ROWB (KPAD * 2)         // 80 bytes per row
#define ASZH (TBM * KPAD)       // halves per stage per matrix
#define STAGEB (ASZH * 2)       // bytes per stage

__device__ __forceinline__ void gemm_core(
        const __half* __restrict__ A,
        const __half* __restrict__ BT,
        void* __restrict__ Cout,
        int M, int N, int K, int mode, __half* gsm) {
    __half* As = gsm;              // 3 * ASZH
    __half* Bs = gsm + 3 * ASZH;   // 3 * ASZH

    int tid = threadIdx.x;
    int wid = tid >> 5, lane = tid & 31;
    int wm = wid >> 2, wn = wid & 3;                // 2 x 4 warp grid
    int m0 = blockIdx.y * TBM, n0 = blockIdx.x * TBN;
    int tg = lane & 3;
    int lm = lane >> 3;   // ldmatrix matrix id 0..3
    int lr = lane & 7;    // row within 8x8 matrix

    float acc[4][4][4];
    #pragma unroll
    for (int i = 0; i < 4; i++)
        #pragma unroll
        for (int j = 0; j < 4; j++)
            #pragma unroll
            for (int t = 0; t < 4; t++) acc[i][j][t] = 0.f;

    auto load_tile = [&](int kt, int buf) {
        int k0 = kt * TBK;
        #pragma unroll
        for (int i = 0; i < 2; i++) {
            int cid = tid + i * 256;
            int row = cid >> 2, c8 = (cid & 3) * 8;
            cp_async16(&As[buf * ASZH + row * KPAD + c8],
                       A + (size_t)(m0 + row) * K + k0 + c8);
            cp_async16(&Bs[buf * ASZH + row * KPAD + c8],
                       BT + (size_t)(n0 + row) * K + k0 + c8);
        }
        cp_commit();
    };

    unsigned aoff = (unsigned)((wm * 64 + (lm & 1) * 8 + lr) * ROWB + (lm >> 1) * 16);
    unsigned boff = (unsigned)((wn * 32 + (lm >> 1) * 8 + lr) * ROWB + (lm & 1) * 16);

    unsigned aBase = smem_u32(As) + aoff;
    unsigned bBase = smem_u32(Bs) + boff;

    int nt = K / TBK;
    load_tile(0, 0);
    load_tile(1, 1);

    for (int kt = 0; kt < nt; kt++) {
        int cur = kt % 3;
        if (kt + 2 < nt) cp_wait<1>(); else cp_wait<0>();
        __syncthreads();
        if (kt + 2 < nt) load_tile(kt + 2, (kt + 2) % 3);

        unsigned aS = aBase + cur * STAGEB;
        unsigned bS = bBase + cur * STAGEB;

        #pragma unroll
        for (int ks = 0; ks < 2; ks++) {
            unsigned kofs = ks * 32;   // 8 words = 32 bytes per k16 step
            unsigned af[4][4];
            #pragma unroll
            for (int mf = 0; mf < 4; mf++)
                ldsm4(af[mf][0], af[mf][1], af[mf][2], af[mf][3],
                      aS + kofs + mf * 16 * ROWB);
            unsigned bf[4][2];
            #pragma unroll
            for (int g = 0; g < 2; g++)
                ldsm4(bf[g*2][0], bf[g*2][1], bf[g*2+1][0], bf[g*2+1][1],
                      bS + kofs + g * 16 * ROWB);
            #pragma unroll
            for (int mf = 0; mf < 4; mf++)
                #pragma unroll
                for (int nf = 0; nf < 4; nf++)
                    mma_f16(acc[mf][nf], af[mf][0], af[mf][1], af[mf][2], af[mf][3],
                            bf[nf][0], bf[nf][1]);
        }
    }

    int crow = m0 + wm * 64 + (lane >> 2);
    int ccol = n0 + wn * 32 + tg * 2;
    #pragma unroll
    for (int mf = 0; mf < 4; mf++) {
        #pragma unroll
        for (int nf = 0; nf < 4; nf++) {
            int r = crow + mf * 16;
            int c = ccol + nf * 8;
            float v0 = acc[mf][nf][0], v1 = acc[mf][nf][1];
            float v2 = acc[mf][nf][2], v3 = acc[mf][nf][3];
            if (mode == 0) {
                __half* Ch = (__half*)Cout;
                *(__half2*)&Ch[(size_t)r * N + c]       = __floats2half2_rn(v0, v1);
                *(__half2*)&Ch[(size_t)(r + 8) * N + c] = __floats2half2_rn(v2, v3);
            } else if (mode == 2) {
                float* Cf = (float*)Cout;
                *(float2*)&Cf[(size_t)r * N + c]       = make_float2(v0, v1);
                *(float2*)&Cf[(size_t)(r + 8) * N + c] = make_float2(v2, v3);
            } else {
                // transposed-per-head store into g_vt[b][n][kv], n = h*64+d
                __half* vt = (__half*)Cout;
                int bb0 = r >> 11, kv0 = r & 2047;
                int bb1 = (r + 8) >> 11, kv1 = (r + 8) & 2047;
                vt[((size_t)(bb0 * 1024 + c)) * 2048 + kv0]     = __float2half(v0);
                vt[((size_t)(bb0 * 1024 + c + 1)) * 2048 + kv0] = __float2half(v1);
                vt[((size_t)(bb1 * 1024 + c)) * 2048 + kv1]     = __float2half(v2);
                vt[((size_t)(bb1 * 1024 + c + 1)) * 2048 + kv1] = __float2half(v3);
            }
        }
    }
}

// Single GEMM (used for the output projection)
__global__ __launch_bounds__(256, 2) void tgemm_kernel(
        const __half* __restrict__ A,
        const __half* __restrict__ BT,
        void* __restrict__ Cout,
        int M, int N, int K, int mode) {
    extern __shared__ __half gsm[];
    gemm_core(A, BT, Cout, M, N, K, mode, gsm);
}

// Fused Q/K/V projection GEMMs: blockIdx.z selects the problem.
__global__ __launch_bounds__(256, 2) void qkv3_kernel(
        const __half* __restrict__ qln,
        const __half* __restrict__ kvln,
        const __half* __restrict__ wq,
        const __half* __restrict__ wk,
        const __half* __restrict__ wv,
        __half* __restrict__ q,
        __half* __restrict__ k,
        __half* __restrict__ vt) {
    extern __shared__ __half gsm[];
    int z = blockIdx.z;
    const __half* A  = (z == 0) ? qln : kvln;
    const __half* BT = (z == 0) ? wq : (z == 1) ? wk : wv;
    void* C          = (z == 0) ? (void*)q : (z == 1) ? (void*)k : (void*)vt;
    int mode         = (z == 2) ? 1 : 0;
    gemm_core(A, BT, C, BATCH * LQQ, DMODEL, DMODEL, mode, gsm);
}

// ---------------------------------------------------------------------------
// Fused L2 norm over q and k: one warp per 64-half head vector.
// ---------------------------------------------------------------------------
__global__ void l2norm2_kernel(__half* __restrict__ q, __half* __restrict__ k, int nvec) {
    int idx  = blockIdx.x * blockDim.x + threadIdx.x;
    int warp = idx >> 5;
    int lane = idx & 31;
    if (warp >= 2 * nvec) return;
    __half* d = (warp < nvec) ? q : k;
    int w = (warp < nvec) ? warp : warp - nvec;
    __half2* p = reinterpret_cast<__half2*>(d) + (size_t)w * 32 + lane;
    float2 f = __half22float2(*p);
    float ss = f.x * f.x + f.y * f.y;
    #pragma unroll
    for (int o = 16; o; o >>= 1) ss += __shfl_xor_sync(0xffffffffu, ss, o);
    float sc = 1.0f / fmaxf(sqrtf(ss), 1e-12f);
    *p = __floats2half2_rn(f.x * sc, f.y * sc);
}

// ---------------------------------------------------------------------------
// Flash attention, fp16 mma + ldmatrix, fixed-max softmax, FA2 register P.
// 8 warps split on m only: warp tile 32 q-rows x 64 kv-cols.
// Q fragments hoisted into registers before the KV loop (loop-invariant).
// ---------------------------------------------------------------------------
#define QROWS 256
#define QP 72
#define QROWB (QP * 2)

__global__ __launch_bounds__(256) void attn_kernel(
        const __half* __restrict__ Q,
        const __half* __restrict__ Kp,
        const __half* __restrict__ Vt,
        const float* __restrict__ maskf,
        const float* __restrict__ tau_p,
        __half* __restrict__ O) {
    extern __shared__ __half smh[];
    __half* Qs = smh;                    // QROWS*QP
    __half* Ks = Qs + QROWS * QP;        // 2 * 64*QP
    __half* Vs = Ks + 2 * 64 * QP;       // 2 * 64*QP
    float*  Ms = (float*)(Vs + 2 * 64 * QP);  // 2 * 64

    int tid  = threadIdx.x;
    int wid  = tid >> 5, lane = tid & 31;
    int q0   = blockIdx.x * QROWS;
    int h    = blockIdx.y;
    int b    = blockIdx.z;
    int tg   = lane & 3;
    int lm   = lane >> 3;
    int lr   = lane & 7;

    float inv_tau = 1.0f / (*tau_p + 1e-6f);
    float MFIX = fabsf(inv_tau);

    const __half* Qbase = Q  + ((size_t)(b * LQQ + q0)) * DMODEL + h * DHEAD;
    const __half* Kbase = Kp + ((size_t)b * LKK) * DMODEL + h * DHEAD;
    const __half* Vbase = Vt + ((size_t)(b * 1024 + h * DHEAD)) * 2048;
    const float*  Mbase = maskf + (size_t)b * LKK;

    #pragma unroll
    for (int i = 0; i < 8; i++) {
        int cid = tid + i * 256;
        int r = cid >> 3, c8 = (cid & 7) * 8;
        cp_async16(&Qs[r * QP + c8], Qbase + (size_t)r * DMODEL + c8);
    }
    cp_commit();

    auto load_kv = [&](int k0, int buf) {
        #pragma unroll
        for (int i = 0; i < 2; i++) {
            int cid = tid + i * 256;
            int r = cid >> 3, c8 = (cid & 7) * 8;
            cp_async16(&Ks[buf * 64 * QP + r * QP + c8],
                       Kbase + (size_t)(k0 + r) * DMODEL + c8);
            cp_async16(&Vs[buf * 64 * QP + r * QP + c8],
                       Vbase + (size_t)r * 2048 + k0 + c8);
        }
        if (tid < 16) cp_async16(&Ms[buf * 64 + tid * 4], Mbase + k0 + tid * 4);
        cp_commit();
    };

    load_kv(0, 0);

    float oacc[2][8][4];
    #pragma unroll
    for (int m = 0; m < 2; m++)
        #pragma unroll
        for (int i = 0; i < 8; i++)
            #pragma unroll
            for (int j = 0; j < 4; j++) oacc[m][i][j] = 0.f;
    float lsum[2][2] = {};

    unsigned aoff = (unsigned)((wid * 32 + (lm & 1) * 8 + lr) * QROWB + (lm >> 1) * 16);
    unsigned boff = (unsigned)(((lm >> 1) * 8 + lr) * QROWB + (lm & 1) * 16);
    unsigned qA = smem_u32(Qs) + aoff;
    unsigned kB = smem_u32(Ks) + boff;
    unsigned vB = smem_u32(Vs) + boff;
    const unsigned KVSTAGE = 64 * QP * 2;

    // Hoist loop-invariant Q fragments into registers:
    // wait for the Q cp.async group (and KV tile 0, committed after) to land.
    cp_wait<0>();
    __syncthreads();
    unsigned qf[4][2][4];   // [ks][mf][reg]
    #pragma unroll
    for (int ks = 0; ks < 4; ks++) {
        unsigned kofs = ks * 32;
        #pragma unroll
        for (int mf = 0; mf < 2; mf++)
            ldsm4(qf[ks][mf][0], qf[ks][mf][1], qf[ks][mf][2], qf[ks][mf][3],
                  qA + kofs + mf * 16 * QROWB);
    }

    const int NT = LKK / 64;
    for (int kt = 0; kt < NT; kt++) {
        int cur = kt & 1;
        cp_wait<0>();
        __syncthreads();
        if (kt + 1 < NT) load_kv((kt + 1) * 64, cur ^ 1);

        unsigned kS = kB + cur * KVSTAGE;
        unsigned vS = vB + cur * KVSTAGE;
        const float* Msb = Ms + cur * 64;

        float sacc[2][8][4];
        #pragma unroll
        for (int m = 0; m < 2; m++)
            #pragma unroll
            for (int i = 0; i < 8; i++)
                #pragma unroll
                for (int j = 0; j < 4; j++) sacc[m][i][j] = 0.f;

        #pragma unroll
        for (int ks = 0; ks < 4; ks++) {
            unsigned kofs = ks * 32;
            unsigned bf[8][2];
            #pragma unroll
            for (int g = 0; g < 4; g++)
                ldsm4(bf[g*2][0], bf[g*2][1], bf[g*2+1][0], bf[g*2+1][1],
                      kS + kofs + g * 16 * QROWB);
            #pragma unroll
            for (int mf = 0; mf < 2; mf++) {
                #pragma unroll
                for (int nf = 0; nf < 8; nf++)
                    mma_f16(sacc[mf][nf], qf[ks][mf][0], qf[ks][mf][1],
                            qf[ks][mf][2], qf[ks][mf][3], bf[nf][0], bf[nf][1]);
            }
        }

        unsigned ph[2][8][2];
        #pragma unroll
        for (int mf = 0; mf < 2; mf++) {
            #pragma unroll
            for (int nf = 0; nf < 8; nf++) {
                int c = nf * 8 + tg * 2;
                float mk0 = Msb[c], mk1 = Msb[c + 1];
                float p00 = __expf(fminf(sacc[mf][nf][0] * inv_tau - MFIX, 0.f)) * mk0;
                float p01 = __expf(fminf(sacc[mf][nf][1] * inv_tau - MFIX, 0.f)) * mk1;
                float p10 = __expf(fminf(sacc[mf][nf][2] * inv_tau - MFIX, 0.f)) * mk0;
                float p11 = __expf(fminf(sacc[mf][nf][3] * inv_tau - MFIX, 0.f)) * mk1;
                lsum[mf][0] += p00 + p01;
                lsum[mf][1] += p10 + p11;
                ph[mf][nf][0] = packh2(p00, p01);
                ph[mf][nf][1] = packh2(p10, p11);
            }
        }

        #pragma unroll
        for (int ks = 0; ks < 4; ks++) {
            unsigned kofs = ks * 32;
            unsigned bf[8][2];
            #pragma unroll
            for (int g = 0; g < 4; g++)
                ldsm4(bf[g*2][0], bf[g*2][1], bf[g*2+1][0], bf[g*2+1][1],
                      vS + kofs + g * 16 * QROWB);
            #pragma unroll
            for (int mf = 0; mf < 2; mf++) {
                unsigned a0 = ph[mf][2*ks][0];
                unsigned a1 = ph[mf][2*ks][1];
                unsigned a2 = ph[mf][2*ks+1][0];
                unsigned a3 = ph[mf][2*ks+1][1];
                #pragma unroll
                for (int nf = 0; nf < 8; nf++)
                    mma_f16(oacc[mf][nf], a0, a1, a2, a3, bf[nf][0], bf[nf][1]);
            }
        }
    }

    #pragma unroll
    for (int mf = 0; mf < 2; mf++) {
        lsum[mf][0] += __shfl_xor_sync(0xffffffffu, lsum[mf][0], 1);
        lsum[mf][0] += __shfl_xor_sync(0xffffffffu, lsum[mf][0], 2);
        lsum[mf][1] += __shfl_xor_sync(0xffffffffu, lsum[mf][1], 1);
        lsum[mf][1] += __shfl_xor_sync(0xffffffffu, lsum[mf][1], 2);
    }

    int rA = wid * 32 + (lane >> 2);
    #pragma unroll
    for (int mf = 0; mf < 2; mf++) {
        int r0 = rA + mf * 16;
        float li0 = 1.0f / lsum[mf][0];
        float li1 = 1.0f / lsum[mf][1];
        int gcol = h * DHEAD + tg * 2;
        #pragma unroll
        for (int nf = 0; nf < 8; nf++) {
            size_t base0 = ((size_t)(b * LQQ + q0 + r0)) * DMODEL + gcol + nf * 8;
            size_t base1 = ((size_t)(b * LQQ + q0 + r0 + 8)) * DMODEL + gcol + nf * 8;
            *(__half2*)&O[base0] = __floats2half2_rn(oacc[mf][nf][0] * li0,
                                                     oacc[mf][nf][1] * li0);
            *(__half2*)&O[base1] = __floats2half2_rn(oacc[mf][nf][2] * li1,
                                                     oacc[mf][nf][3] * li1);
        }
    }
}

// ---------------------------------------------------------------------------
// Launcher
// ---------------------------------------------------------------------------
extern "C" void kernel_launch(void* const* d_in, const int* in_sizes, int n_in,
                              void* d_out, int out_size) {
    const float* x     = (const float*)d_in[0];
    const float* ctx   = (const float*)d_in[1];
    const void*  mask  = d_in[2];
    const float* lnqw  = (const float*)d_in[3];
    const float* lnqb  = (const float*)d_in[4];
    const float* lncw  = (const float*)d_in[5];
    const float* lncb  = (const float*)d_in[6];
    const float* Wq    = (const float*)d_in[7];
    const float* Wk    = (const float*)d_in[8];
    const float* Wv    = (const float*)d_in[9];
    const float* Wo    = (const float*)d_in[10];
    const float* taup  = (const float*)d_in[11];
    float* out = (float*)d_out;

    __half *qln, *kvln, *q, *k, *vt, *ao, *wq, *wk, *wv, *wo;
    float *maskf;
    cudaGetSymbolAddress((void**)&qln,   g_qln);
    cudaGetSymbolAddress((void**)&kvln,  g_kvln);
    cudaGetSymbolAddress((void**)&q,     g_q);
    cudaGetSymbolAddress((void**)&k,     g_k);
    cudaGetSymbolAddress((void**)&vt,    g_vt);
    cudaGetSymbolAddress((void**)&ao,    g_ao);
    cudaGetSymbolAddress((void**)&maskf, g_maskf);
    cudaGetSymbolAddress((void**)&wq,    g_wq);
    cudaGetSymbolAddress((void**)&wk,    g_wk);
    cudaGetSymbolAddress((void**)&wv,    g_wv);
    cudaGetSymbolAddress((void**)&wo,    g_wo);

    // GEMM dynamic smem (3-stage, halves)
    const int smem_gemm = (int)(6 * ASZH * sizeof(__half));
    cudaFuncSetAttribute(tgemm_kernel, cudaFuncAttributeMaxDynamicSharedMemorySize, smem_gemm);
    cudaFuncSetAttribute(qkv3_kernel,  cudaFuncAttributeMaxDynamicSharedMemorySize, smem_gemm);

    // attention dynamic smem (no P buffer)
    const int smem_attn = (int)((QROWS * QP + 2 * 64 * QP + 2 * 64 * QP) * sizeof(__half)
                              + 128 * sizeof(float));
    cudaFuncSetAttribute(attn_kernel, cudaFuncAttributeMaxDynamicSharedMemorySize, smem_attn);

    detect_mask_kernel<<<1, 256>>>((const unsigned char*)mask);
    maskf_kernel<<<(BATCH * LKK + 255) / 256, 256>>>(mask);

    // fused transpose + fp16-convert of all 4 weights (one launch)
    dim3 wtb(32, 8), wtg(DMODEL / 32, DMODEL / 32, 4);
    wtrans4_kernel<<<wtg, wtb>>>(Wq, wq, Wk, wk, Wv, wv, Wo, wo);

    // fused LayerNorm for x and context (one launch)
    ln2_kernel<<<BATCH * (LQQ + LKK), 256>>>(x, ctx, lnqw, lnqb, lncw, lncb, qln, kvln);

    // fused Q/K/V projection GEMMs (one launch, z selects the problem)
    dim3 gqkv(DMODEL / TBN, (BATCH * LQQ) / TBM, 3);
    qkv3_kernel<<<gqkv, 256, smem_gemm>>>(qln, kvln, wq, wk, wv, q, k, vt);

    // fused l2 norm of q and k (one launch)
    int nvec = BATCH * LQQ * NHEAD;
    l2norm2_kernel<<<(2 * nvec * 32) / 256, 256>>>(q, k, nvec);

    attn_kernel<<<dim3(LQQ / QROWS, NHEAD, BATCH), 256, smem_attn>>>(q, k, vt, maskf, taup, ao);

    dim3 gg(DMODEL / TBN, (BATCH * LQQ) / TBM);
    tgemm_kernel<<<gg, 256, smem_gemm>>>(ao, wo, out, BATCH * LQQ, DMODEL, DMODEL, 2);
}

// round 14
// speedup vs baseline: 1.0308x; 1.0308x over previous
#include <cuda_runtime.h>
#include <cuda_fp16.h>
#include <math.h>

// Problem constants
#define BATCH 4
#define LQQ   2048
#define LKK   2048
#define DMODEL 1024
#define NHEAD 16
#define DHEAD 64

// Scratch (static device arrays -- no runtime allocation allowed)
__device__ __half g_qln [BATCH * LQQ * DMODEL];
__device__ __half g_kvln[BATCH * LKK * DMODEL];
__device__ __half g_q   [BATCH * LQQ * DMODEL];
__device__ __half g_k   [BATCH * LKK * DMODEL];
__device__ __half g_vt  [BATCH * NHEAD * DHEAD * LKK];  // [b][h][d][kv]
__device__ __half g_ao  [BATCH * LQQ * DMODEL];
__device__ __half g_wq  [DMODEL * DMODEL];  // transposed [N][K]
__device__ __half g_wk  [DMODEL * DMODEL];
__device__ __half g_wv  [DMODEL * DMODEL];
__device__ __half g_wo  [DMODEL * DMODEL];
__device__ float  g_maskf[BATCH * LKK];   // 0.0 = masked, 1.0 = keep
__device__ int    g_mask_mode;            // 0=uint8, 1=int32, 2=float32

// ---------------------------------------------------------------------------
// mma / cp.async / ldmatrix helpers
// ---------------------------------------------------------------------------
__device__ __forceinline__ void mma_f16(float c[4],
                                        unsigned a0, unsigned a1, unsigned a2, unsigned a3,
                                        unsigned b0, unsigned b1) {
    asm volatile(
        "mma.sync.aligned.m16n8k16.row.col.f32.f16.f16.f32 "
        "{%0,%1,%2,%3},{%4,%5,%6,%7},{%8,%9},{%0,%1,%2,%3};"
        : "+f"(c[0]), "+f"(c[1]), "+f"(c[2]), "+f"(c[3])
        : "r"(a0), "r"(a1), "r"(a2), "r"(a3), "r"(b0), "r"(b1));
}

__device__ __forceinline__ void cp_async16(void* smem_dst, const void* gmem_src) {
    unsigned sa = (unsigned)__cvta_generic_to_shared(smem_dst);
    asm volatile("cp.async.cg.shared.global [%0], [%1], 16;" :: "r"(sa), "l"(gmem_src));
}
__device__ __forceinline__ void cp_commit() {
    asm volatile("cp.async.commit_group;");
}
template <int N>
__device__ __forceinline__ void cp_wait() {
    asm volatile("cp.async.wait_group %0;" :: "n"(N));
}

__device__ __forceinline__ unsigned smem_u32(const void* p) {
    return (unsigned)__cvta_generic_to_shared(p);
}
__device__ __forceinline__ void ldsm4(unsigned& d0, unsigned& d1,
                                      unsigned& d2, unsigned& d3, unsigned saddr) {
    asm volatile("ldmatrix.sync.aligned.m8n8.x4.shared.b16 {%0,%1,%2,%3}, [%4];"
                 : "=r"(d0), "=r"(d1), "=r"(d2), "=r"(d3) : "r"(saddr));
}
__device__ __forceinline__ unsigned packh2(float a, float b) {
    __half2 h = __floats2half2_rn(a, b);
    return *(unsigned*)&h;
}

// ---------------------------------------------------------------------------
// Mask dtype detection (bool array may arrive as u8/i32/f32)
// ---------------------------------------------------------------------------
__global__ void detect_mask_kernel(const unsigned char* __restrict__ m) {
    __shared__ int nz[4];
    if (threadIdx.x < 4) nz[threadIdx.x] = 0;
    __syncthreads();
    int loc = 0;
    for (int i = threadIdx.x; i < 8192; i += blockDim.x)
        if (m[i]) loc = 1;
    if (loc) atomicOr(&nz[threadIdx.x & 3], 1);
    __syncthreads();
    if (threadIdx.x == 0) {
        int mode;
        int tot = nz[0] | nz[1] | nz[2] | nz[3];
        if (!tot)                          mode = 0;
        else if (!(nz[1] | nz[2] | nz[3])) mode = 1; // int32 LE
        else if (!(nz[0] | nz[1]))         mode = 2; // float32 (0x3F800000)
        else                               mode = 0; // uint8/bool
        g_mask_mode = mode;
    }
}

// Convert mask (any dtype) into multiplicative float mask: 0 = masked, 1 = keep
__global__ void maskf_kernel(const void* __restrict__ m) {
    int i = blockIdx.x * blockDim.x + threadIdx.x;
    if (i >= BATCH * LKK) return;
    int mode = g_mask_mode;
    bool mm = (mode == 0) ? (((const unsigned char*)m)[i] != 0)
            : (mode == 1) ? (((const int*)m)[i] != 0)
                          : (((const float*)m)[i] != 0.f);
    g_maskf[i] = mm ? 0.f : 1.f;
}

// ---------------------------------------------------------------------------
// Fused weight transpose + fp16 convert for all 4 weights.
// ---------------------------------------------------------------------------
__global__ void wtrans4_kernel(const float* __restrict__ W0, __half* __restrict__ T0,
                               const float* __restrict__ W1, __half* __restrict__ T1,
                               const float* __restrict__ W2, __half* __restrict__ T2,
                               const float* __restrict__ W3, __half* __restrict__ T3) {
    const float* W = (blockIdx.z == 0) ? W0 : (blockIdx.z == 1) ? W1
                   : (blockIdx.z == 2) ? W2 : W3;
    __half* WT     = (blockIdx.z == 0) ? T0 : (blockIdx.z == 1) ? T1
                   : (blockIdx.z == 2) ? T2 : T3;
    __shared__ float t[32][33];
    int n0 = blockIdx.x * 32, k0 = blockIdx.y * 32;
    #pragma unroll
    for (int i = 0; i < 4; i++) {
        int k = threadIdx.y + i * 8;
        t[k][threadIdx.x] = W[(size_t)(k0 + k) * DMODEL + n0 + threadIdx.x];
    }
    __syncthreads();
    #pragma unroll
    for (int i = 0; i < 4; i++) {
        int n = threadIdx.y + i * 8;
        WT[(size_t)(n0 + n) * DMODEL + k0 + threadIdx.x] = __float2half(t[threadIdx.x][n]);
    }
}

// ---------------------------------------------------------------------------
// Fused LayerNorm for x and context. Output fp16.
// ---------------------------------------------------------------------------
__global__ void ln2_kernel(const float* __restrict__ x,
                           const float* __restrict__ ctx,
                           const float* __restrict__ wq_, const float* __restrict__ bq_,
                           const float* __restrict__ wc_, const float* __restrict__ bc_,
                           __half* __restrict__ oq_, __half* __restrict__ oc_) {
    int row = blockIdx.x;
    bool isq = row < BATCH * LQQ;
    const float* src = isq ? x : ctx;
    const float* w   = isq ? wq_ : wc_;
    const float* bia = isq ? bq_ : bc_;
    __half* out      = isq ? oq_ : oc_;
    int r = isq ? row : row - BATCH * LQQ;

    int tid = threadIdx.x;
    const float4* xr = reinterpret_cast<const float4*>(src + (size_t)r * DMODEL);
    float4 a = xr[tid];
    float s  = a.x + a.y + a.z + a.w;
    float ss = a.x * a.x + a.y * a.y + a.z * a.z + a.w * a.w;

    __shared__ float rs[8], rss[8], stats[2];
    #pragma unroll
    for (int o = 16; o; o >>= 1) {
        s  += __shfl_xor_sync(0xffffffffu, s,  o);
        ss += __shfl_xor_sync(0xffffffffu, ss, o);
    }
    int wid = tid >> 5, lane = tid & 31;
    if (!lane) { rs[wid] = s; rss[wid] = ss; }
    __syncthreads();
    if (tid == 0) {
        float S = 0.f, SS = 0.f;
        #pragma unroll
        for (int i = 0; i < 8; i++) { S += rs[i]; SS += rss[i]; }
        float mean = S * (1.0f / DMODEL);
        float var  = SS * (1.0f / DMODEL) - mean * mean;
        stats[0] = mean;
        stats[1] = rsqrtf(var + 1e-5f);
    }
    __syncthreads();
    float mean = stats[0], rstd = stats[1];
    float4 wv = reinterpret_cast<const float4*>(w)[tid];
    float4 bv = reinterpret_cast<const float4*>(bia)[tid];
    __half2 h0 = __floats2half2_rn((a.x - mean) * rstd * wv.x + bv.x,
                                   (a.y - mean) * rstd * wv.y + bv.y);
    __half2 h1 = __floats2half2_rn((a.z - mean) * rstd * wv.z + bv.z,
                                   (a.w - mean) * rstd * wv.w + bv.w);
    __half2* orow = reinterpret_cast<__half2*>(out + (size_t)r * DMODEL);
    orow[tid * 2]     = h0;
    orow[tid * 2 + 1] = h1;
}

// ---------------------------------------------------------------------------
// fp16 tensor-core GEMM core, cp.async 3-stage pipeline, ldmatrix loads.
// ---------------------------------------------------------------------------
#define TBM 128
#define TBN 128
#define TBK 32
#define KPAD 40
#define ROWB (KPAD * 2)
#define ASZH (TBM * KPAD)
#define STAGEB (ASZH * 2)

__device__ __forceinline__ void gemm_core(
        const __half* __restrict__ A,
        const __half* __restrict__ BT,
        void* __restrict__ Cout,
        int M, int N, int K, int mode, __half* gsm) {
    __half* As = gsm;
    __half* Bs = gsm + 3 * ASZH;

    int tid = threadIdx.x;
    int wid = tid >> 5, lane = tid & 31;
    int wm = wid >> 2, wn = wid & 3;
    int m0 = blockIdx.y * TBM, n0 = blockIdx.x * TBN;
    int tg = lane & 3;
    int lm = lane >> 3;
    int lr = lane & 7;

    float acc[4][4][4];
    #pragma unroll
    for (int i = 0; i < 4; i++)
        #pragma unroll
        for (int j = 0; j < 4; j++)
            #pragma unroll
            for (int t = 0; t < 4; t++) acc[i][j][t] = 0.f;

    auto load_tile = [&](int kt, int buf) {
        int k0 = kt * TBK;
        #pragma unroll
        for (int i = 0; i < 2; i++) {
            int cid = tid + i * 256;
            int row = cid >> 2, c8 = (cid & 3) * 8;
            cp_async16(&As[buf * ASZH + row * KPAD + c8],
                       A + (size_t)(m0 + row) * K + k0 + c8);
            cp_async16(&Bs[buf * ASZH + row * KPAD + c8],
                       BT + (size_t)(n0 + row) * K + k0 + c8);
        }
        cp_commit();
    };

    unsigned aoff = (unsigned)((wm * 64 + (lm & 1) * 8 + lr) * ROWB + (lm >> 1) * 16);
    unsigned boff = (unsigned)((wn * 32 + (lm >> 1) * 8 + lr) * ROWB + (lm & 1) * 16);

    unsigned aBase = smem_u32(As) + aoff;
    unsigned bBase = smem_u32(Bs) + boff;

    int nt = K / TBK;
    load_tile(0, 0);
    load_tile(1, 1);

    for (int kt = 0; kt < nt; kt++) {
        int cur = kt % 3;
        if (kt + 2 < nt) cp_wait<1>(); else cp_wait<0>();
        __syncthreads();
        if (kt + 2 < nt) load_tile(kt + 2, (kt + 2) % 3);

        unsigned aS = aBase + cur * STAGEB;
        unsigned bS = bBase + cur * STAGEB;

        #pragma unroll
        for (int ks = 0; ks < 2; ks++) {
            unsigned kofs = ks * 32;
            unsigned af[4][4];
            #pragma unroll
            for (int mf = 0; mf < 4; mf++)
                ldsm4(af[mf][0], af[mf][1], af[mf][2], af[mf][3],
                      aS + kofs + mf * 16 * ROWB);
            unsigned bf[4][2];
            #pragma unroll
            for (int g = 0; g < 2; g++)
                ldsm4(bf[g*2][0], bf[g*2][1], bf[g*2+1][0], bf[g*2+1][1],
                      bS + kofs + g * 16 * ROWB);
            #pragma unroll
            for (int mf = 0; mf < 4; mf++)
                #pragma unroll
                for (int nf = 0; nf < 4; nf++)
                    mma_f16(acc[mf][nf], af[mf][0], af[mf][1], af[mf][2], af[mf][3],
                            bf[nf][0], bf[nf][1]);
        }
    }

    int crow = m0 + wm * 64 + (lane >> 2);
    int ccol = n0 + wn * 32 + tg * 2;
    #pragma unroll
    for (int mf = 0; mf < 4; mf++) {
        #pragma unroll
        for (int nf = 0; nf < 4; nf++) {
            int r = crow + mf * 16;
            int c = ccol + nf * 8;
            float v0 = acc[mf][nf][0], v1 = acc[mf][nf][1];
            float v2 = acc[mf][nf][2], v3 = acc[mf][nf][3];
            if (mode == 0) {
                __half* Ch = (__half*)Cout;
                *(__half2*)&Ch[(size_t)r * N + c]       = __floats2half2_rn(v0, v1);
                *(__half2*)&Ch[(size_t)(r + 8) * N + c] = __floats2half2_rn(v2, v3);
            } else if (mode == 2) {
                float* Cf = (float*)Cout;
                *(float2*)&Cf[(size_t)r * N + c]       = make_float2(v0, v1);
                *(float2*)&Cf[(size_t)(r + 8) * N + c] = make_float2(v2, v3);
            } else {
                __half* vt = (__half*)Cout;
                int bb0 = r >> 11, kv0 = r & 2047;
                int bb1 = (r + 8) >> 11, kv1 = (r + 8) & 2047;
                vt[((size_t)(bb0 * 1024 + c)) * 2048 + kv0]     = __float2half(v0);
                vt[((size_t)(bb0 * 1024 + c + 1)) * 2048 + kv0] = __float2half(v1);
                vt[((size_t)(bb1 * 1024 + c)) * 2048 + kv1]     = __float2half(v2);
                vt[((size_t)(bb1 * 1024 + c + 1)) * 2048 + kv1] = __float2half(v3);
            }
        }
    }
}

__global__ __launch_bounds__(256, 2) void tgemm_kernel(
        const __half* __restrict__ A,
        const __half* __restrict__ BT,
        void* __restrict__ Cout,
        int M, int N, int K, int mode) {
    extern __shared__ __half gsm[];
    gemm_core(A, BT, Cout, M, N, K, mode, gsm);
}

__global__ __launch_bounds__(256, 2) void qkv3_kernel(
        const __half* __restrict__ qln,
        const __half* __restrict__ kvln,
        const __half* __restrict__ wq,
        const __half* __restrict__ wk,
        const __half* __restrict__ wv,
        __half* __restrict__ q,
        __half* __restrict__ k,
        __half* __restrict__ vt) {
    extern __shared__ __half gsm[];
    int z = blockIdx.z;
    const __half* A  = (z == 0) ? qln : kvln;
    const __half* BT = (z == 0) ? wq : (z == 1) ? wk : wv;
    void* C          = (z == 0) ? (void*)q : (z == 1) ? (void*)k : (void*)vt;
    int mode         = (z == 2) ? 1 : 0;
    gemm_core(A, BT, C, BATCH * LQQ, DMODEL, DMODEL, mode, gsm);
}

// ---------------------------------------------------------------------------
// Fused L2 norm over q and k: one warp per 64-half head vector.
// ---------------------------------------------------------------------------
__global__ void l2norm2_kernel(__half* __restrict__ q, __half* __restrict__ k, int nvec) {
    int idx  = blockIdx.x * blockDim.x + threadIdx.x;
    int warp = idx >> 5;
    int lane = idx & 31;
    if (warp >= 2 * nvec) return;
    __half* d = (warp < nvec) ? q : k;
    int w = (warp < nvec) ? warp : warp - nvec;
    __half2* p = reinterpret_cast<__half2*>(d) + (size_t)w * 32 + lane;
    float2 f = __half22float2(*p);
    float ss = f.x * f.x + f.y * f.y;
    #pragma unroll
    for (int o = 16; o; o >>= 1) ss += __shfl_xor_sync(0xffffffffu, ss, o);
    float sc = 1.0f / fmaxf(sqrtf(ss), 1e-12f);
    *p = __floats2half2_rn(f.x * sc, f.y * sc);
}

// ---------------------------------------------------------------------------
// Flash attention, fp16 mma + ldmatrix, fixed-max softmax, FA2 register P.
// 8 warps split on m only: warp tile 32 q-rows x 64 kv-cols.
// 128-key cp.async stages, computed as TWO 64-key passes per barrier.
// ---------------------------------------------------------------------------
#define QROWS 256
#define QP 72
#define QROWB (QP * 2)     // 144 B: Q and K row stride
#define VP 136
#define VROWB (VP * 2)     // 272 B: V row stride (64 d-rows x 128 kv-cols)
#define KSTAGE (128 * QP * 2)   // bytes per K buffer
#define VSTAGE (64 * VP * 2)    // bytes per V buffer

__global__ __launch_bounds__(256) void attn_kernel(
        const __half* __restrict__ Q,
        const __half* __restrict__ Kp,
        const __half* __restrict__ Vt,
        const float* __restrict__ maskf,
        const float* __restrict__ tau_p,
        __half* __restrict__ O) {
    extern __shared__ __half smh[];
    __half* Qs = smh;                    // QROWS*QP
    __half* Ks = Qs + QROWS * QP;        // 2 * 128*QP
    __half* Vs = Ks + 2 * 128 * QP;      // 2 * 64*VP
    float*  Ms = (float*)(Vs + 2 * 64 * VP);  // 2 * 128

    int tid  = threadIdx.x;
    int wid  = tid >> 5, lane = tid & 31;
    int q0   = blockIdx.x * QROWS;
    int h    = blockIdx.y;
    int b    = blockIdx.z;
    int tg   = lane & 3;
    int lm   = lane >> 3;
    int lr   = lane & 7;

    float inv_tau = 1.0f / (*tau_p + 1e-6f);
    float MFIX = fabsf(inv_tau);

    const __half* Qbase = Q  + ((size_t)(b * LQQ + q0)) * DMODEL + h * DHEAD;
    const __half* Kbase = Kp + ((size_t)b * LKK) * DMODEL + h * DHEAD;
    const __half* Vbase = Vt + ((size_t)(b * 1024 + h * DHEAD)) * 2048;
    const float*  Mbase = maskf + (size_t)b * LKK;

    #pragma unroll
    for (int i = 0; i < 8; i++) {
        int cid = tid + i * 256;
        int r = cid >> 3, c8 = (cid & 7) * 8;
        cp_async16(&Qs[r * QP + c8], Qbase + (size_t)r * DMODEL + c8);
    }
    cp_commit();

    // Load a 128-key stage: K 128x64, V 64x128, mask 128 floats.
    auto load_kv = [&](int k0, int buf) {
        #pragma unroll
        for (int i = 0; i < 4; i++) {
            int cid = tid + i * 256;
            int rk = cid >> 3, ck = (cid & 7) * 8;    // K: 128 rows x 64 cols
            cp_async16(&Ks[buf * 128 * QP + rk * QP + ck],
                       Kbase + (size_t)(k0 + rk) * DMODEL + ck);
            int rv = cid >> 4, cv = (cid & 15) * 8;   // V: 64 rows x 128 cols
            cp_async16(&Vs[buf * 64 * VP + rv * VP + cv],
                       Vbase + (size_t)rv * 2048 + k0 + cv);
        }
        if (tid < 32) cp_async16(&Ms[buf * 128 + tid * 4], Mbase + k0 + tid * 4);
        cp_commit();
    };

    load_kv(0, 0);

    float oacc[2][8][4];
    #pragma unroll
    for (int m = 0; m < 2; m++)
        #pragma unroll
        for (int i = 0; i < 8; i++)
            #pragma unroll
            for (int j = 0; j < 4; j++) oacc[m][i][j] = 0.f;
    float lsum[2][2] = {};

    unsigned aoff  = (unsigned)((wid * 32 + (lm & 1) * 8 + lr) * QROWB + (lm >> 1) * 16);
    unsigned boffK = (unsigned)(((lm >> 1) * 8 + lr) * QROWB + (lm & 1) * 16);
    unsigned boffV = (unsigned)(((lm >> 1) * 8 + lr) * VROWB + (lm & 1) * 16);
    unsigned qA = smem_u32(Qs) + aoff;
    unsigned kB = smem_u32(Ks) + boffK;
    unsigned vB = smem_u32(Vs) + boffV;

    const int NT = LKK / 128;
    for (int kt = 0; kt < NT; kt++) {
        int cur = kt & 1;
        cp_wait<0>();
        __syncthreads();
        if (kt + 1 < NT) load_kv((kt + 1) * 128, cur ^ 1);

        #pragma unroll
        for (int p = 0; p < 2; p++) {
            unsigned kS = kB + cur * KSTAGE + p * 64 * QROWB;  // 64-row sub-tile
            unsigned vS = vB + cur * VSTAGE + p * 128;          // 64 kv-cols = 128 B
            const float* Msb = Ms + cur * 128 + p * 64;

            float sacc[2][8][4];
            #pragma unroll
            for (int m = 0; m < 2; m++)
                #pragma unroll
                for (int i = 0; i < 8; i++)
                    #pragma unroll
                    for (int j = 0; j < 4; j++) sacc[m][i][j] = 0.f;

            #pragma unroll
            for (int ks = 0; ks < 4; ks++) {
                unsigned kofs = ks * 32;
                unsigned bf[8][2];
                #pragma unroll
                for (int g = 0; g < 4; g++)
                    ldsm4(bf[g*2][0], bf[g*2][1], bf[g*2+1][0], bf[g*2+1][1],
                          kS + kofs + g * 16 * QROWB);
                #pragma unroll
                for (int mf = 0; mf < 2; mf++) {
                    unsigned a0, a1, a2, a3;
                    ldsm4(a0, a1, a2, a3, qA + kofs + mf * 16 * QROWB);
                    #pragma unroll
                    for (int nf = 0; nf < 8; nf++)
                        mma_f16(sacc[mf][nf], a0, a1, a2, a3, bf[nf][0], bf[nf][1]);
                }
            }

            unsigned ph[2][8][2];
            #pragma unroll
            for (int mf = 0; mf < 2; mf++) {
                #pragma unroll
                for (int nf = 0; nf < 8; nf++) {
                    int c = nf * 8 + tg * 2;
                    float mk0 = Msb[c], mk1 = Msb[c + 1];
                    float p00 = __expf(fminf(sacc[mf][nf][0] * inv_tau - MFIX, 0.f)) * mk0;
                    float p01 = __expf(fminf(sacc[mf][nf][1] * inv_tau - MFIX, 0.f)) * mk1;
                    float p10 = __expf(fminf(sacc[mf][nf][2] * inv_tau - MFIX, 0.f)) * mk0;
                    float p11 = __expf(fminf(sacc[mf][nf][3] * inv_tau - MFIX, 0.f)) * mk1;
                    lsum[mf][0] += p00 + p01;
                    lsum[mf][1] += p10 + p11;
                    ph[mf][nf][0] = packh2(p00, p01);
                    ph[mf][nf][1] = packh2(p10, p11);
                }
            }

            #pragma unroll
            for (int ks = 0; ks < 4; ks++) {
                unsigned kofs = ks * 32;
                unsigned bf[8][2];
                #pragma unroll
                for (int g = 0; g < 4; g++)
                    ldsm4(bf[g*2][0], bf[g*2][1], bf[g*2+1][0], bf[g*2+1][1],
                          vS + kofs + g * 16 * VROWB);
                #pragma unroll
                for (int mf = 0; mf < 2; mf++) {
                    unsigned a0 = ph[mf][2*ks][0];
                    unsigned a1 = ph[mf][2*ks][1];
                    unsigned a2 = ph[mf][2*ks+1][0];
                    unsigned a3 = ph[mf][2*ks+1][1];
                    #pragma unroll
                    for (int nf = 0; nf < 8; nf++)
                        mma_f16(oacc[mf][nf], a0, a1, a2, a3, bf[nf][0], bf[nf][1]);
                }
            }
        }
    }

    #pragma unroll
    for (int mf = 0; mf < 2; mf++) {
        lsum[mf][0] += __shfl_xor_sync(0xffffffffu, lsum[mf][0], 1);
        lsum[mf][0] += __shfl_xor_sync(0xffffffffu, lsum[mf][0], 2);
        lsum[mf][1] += __shfl_xor_sync(0xffffffffu, lsum[mf][1], 1);
        lsum[mf][1] += __shfl_xor_sync(0xffffffffu, lsum[mf][1], 2);
    }

    int rA = wid * 32 + (lane >> 2);
    #pragma unroll
    for (int mf = 0; mf < 2; mf++) {
        int r0 = rA + mf * 16;
        float li0 = 1.0f / lsum[mf][0];
        float li1 = 1.0f / lsum[mf][1];
        int gcol = h * DHEAD + tg * 2;
        #pragma unroll
        for (int nf = 0; nf < 8; nf++) {
            size_t base0 = ((size_t)(b * LQQ + q0 + r0)) * DMODEL + gcol + nf * 8;
            size_t base1 = ((size_t)(b * LQQ + q0 + r0 + 8)) * DMODEL + gcol + nf * 8;
            *(__half2*)&O[base0] = __floats2half2_rn(oacc[mf][nf][0] * li0,
                                                     oacc[mf][nf][1] * li0);
            *(__half2*)&O[base1] = __floats2half2_rn(oacc[mf][nf][2] * li1,
                                                     oacc[mf][nf][3] * li1);
        }
    }
}

// ---------------------------------------------------------------------------
// Launcher
// ---------------------------------------------------------------------------
extern "C" void kernel_launch(void* const* d_in, const int* in_sizes, int n_in,
                              void* d_out, int out_size) {
    const float* x     = (const float*)d_in[0];
    const float* ctx   = (const float*)d_in[1];
    const void*  mask  = d_in[2];
    const float* lnqw  = (const float*)d_in[3];
    const float* lnqb  = (const float*)d_in[4];
    const float* lncw  = (const float*)d_in[5];
    const float* lncb  = (const float*)d_in[6];
    const float* Wq    = (const float*)d_in[7];
    const float* Wk    = (const float*)d_in[8];
    const float* Wv    = (const float*)d_in[9];
    const float* Wo    = (const float*)d_in[10];
    const float* taup  = (const float*)d_in[11];
    float* out = (float*)d_out;

    __half *qln, *kvln, *q, *k, *vt, *ao, *wq, *wk, *wv, *wo;
    float *maskf;
    cudaGetSymbolAddress((void**)&qln,   g_qln);
    cudaGetSymbolAddress((void**)&kvln,  g_kvln);
    cudaGetSymbolAddress((void**)&q,     g_q);
    cudaGetSymbolAddress((void**)&k,     g_k);
    cudaGetSymbolAddress((void**)&vt,    g_vt);
    cudaGetSymbolAddress((void**)&ao,    g_ao);
    cudaGetSymbolAddress((void**)&maskf, g_maskf);
    cudaGetSymbolAddress((void**)&wq,    g_wq);
    cudaGetSymbolAddress((void**)&wk,    g_wk);
    cudaGetSymbolAddress((void**)&wv,    g_wv);
    cudaGetSymbolAddress((void**)&wo,    g_wo);

    const int smem_gemm = (int)(6 * ASZH * sizeof(__half));
    cudaFuncSetAttribute(tgemm_kernel, cudaFuncAttributeMaxDynamicSharedMemorySize, smem_gemm);
    cudaFuncSetAttribute(qkv3_kernel,  cudaFuncAttributeMaxDynamicSharedMemorySize, smem_gemm);

    const int smem_attn = (int)((QROWS * QP + 2 * 128 * QP + 2 * 64 * VP) * sizeof(__half)
                              + 2 * 128 * sizeof(float));
    cudaFuncSetAttribute(attn_kernel, cudaFuncAttributeMaxDynamicSharedMemorySize, smem_attn);

    detect_mask_kernel<<<1, 256>>>((const unsigned char*)mask);
    maskf_kernel<<<(BATCH * LKK + 255) / 256, 256>>>(mask);

    dim3 wtb(32, 8), wtg(DMODEL / 32, DMODEL / 32, 4);
    wtrans4_kernel<<<wtg, wtb>>>(Wq, wq, Wk, wk, Wv, wv, Wo, wo);

    ln2_kernel<<<BATCH * (LQQ + LKK), 256>>>(x, ctx, lnqw, lnqb, lncw, lncb, qln, kvln);

    dim3 gqkv(DMODEL / TBN, (BATCH * LQQ) / TBM, 3);
    qkv3_kernel<<<gqkv, 256, smem_gemm>>>(qln, kvln, wq, wk, wv, q, k, vt);

    int nvec = BATCH * LQQ * NHEAD;
    l2norm2_kernel<<<(2 * nvec * 32) / 256, 256>>>(q, k, nvec);

    attn_kernel<<<dim3(LQQ / QROWS, NHEAD, BATCH), 256, smem_attn>>>(q, k, vt, maskf, taup, ao);

    dim3 gg(DMODEL / TBN, (BATCH * LQQ) / TBM);
    tgemm_kernel<<<gg, 256, smem_gemm>>>(ao, wo, out, BATCH * LQQ, DMODEL, DMODEL, 2);
}

// round 15
// speedup vs baseline: 1.0784x; 1.0461x over previous
#include <cuda_runtime.h>
#include <cuda_fp16.h>
#include <math.h>

// Problem constants
#define BATCH 4
#define LQQ   2048
#define LKK   2048
#define DMODEL 1024
#define NHEAD 16
#define DHEAD 64

// Scratch (static device arrays -- no runtime allocation allowed)
__device__ __half g_qln [BATCH * LQQ * DMODEL];
__device__ __half g_kvln[BATCH * LKK * DMODEL];
__device__ __half g_q   [BATCH * LQQ * DMODEL];
__device__ __half g_k   [BATCH * LKK * DMODEL];
__device__ __half g_vt  [BATCH * NHEAD * DHEAD * LKK];  // [b][h][d][kv]
__device__ __half g_ao  [BATCH * LQQ * DMODEL];
__device__ __half g_wq  [DMODEL * DMODEL];  // transposed [N][K]
__device__ __half g_wk  [DMODEL * DMODEL];
__device__ __half g_wv  [DMODEL * DMODEL];
__device__ __half g_wo  [DMODEL * DMODEL];
__device__ float  g_maskf[BATCH * LKK];   // 0.0 = masked, 1.0 = keep
__device__ int    g_mask_mode;            // 0=uint8, 1=int32, 2=float32

// ---------------------------------------------------------------------------
// mma / cp.async / ldmatrix helpers
// ---------------------------------------------------------------------------
__device__ __forceinline__ void mma_f16(float c[4],
                                        unsigned a0, unsigned a1, unsigned a2, unsigned a3,
                                        unsigned b0, unsigned b1) {
    asm volatile(
        "mma.sync.aligned.m16n8k16.row.col.f32.f16.f16.f32 "
        "{%0,%1,%2,%3},{%4,%5,%6,%7},{%8,%9},{%0,%1,%2,%3};"
        : "+f"(c[0]), "+f"(c[1]), "+f"(c[2]), "+f"(c[3])
        : "r"(a0), "r"(a1), "r"(a2), "r"(a3), "r"(b0), "r"(b1));
}

__device__ __forceinline__ void cp_async16(void* smem_dst, const void* gmem_src) {
    unsigned sa = (unsigned)__cvta_generic_to_shared(smem_dst);
    asm volatile("cp.async.cg.shared.global [%0], [%1], 16;" :: "r"(sa), "l"(gmem_src));
}
__device__ __forceinline__ void cp_commit() {
    asm volatile("cp.async.commit_group;");
}
template <int N>
__device__ __forceinline__ void cp_wait() {
    asm volatile("cp.async.wait_group %0;" :: "n"(N));
}

__device__ __forceinline__ unsigned smem_u32(const void* p) {
    return (unsigned)__cvta_generic_to_shared(p);
}
__device__ __forceinline__ void ldsm4(unsigned& d0, unsigned& d1,
                                      unsigned& d2, unsigned& d3, unsigned saddr) {
    asm volatile("ldmatrix.sync.aligned.m8n8.x4.shared.b16 {%0,%1,%2,%3}, [%4];"
                 : "=r"(d0), "=r"(d1), "=r"(d2), "=r"(d3) : "r"(saddr));
}
__device__ __forceinline__ unsigned packh2(float a, float b) {
    __half2 h = __floats2half2_rn(a, b);
    return *(unsigned*)&h;
}
__device__ __forceinline__ float ex2a(float x) {
    float y;
    asm("ex2.approx.f32 %0, %1;" : "=f"(y) : "f"(x));
    return y;
}

// ---------------------------------------------------------------------------
// Mask dtype detection (bool array may arrive as u8/i32/f32)
// ---------------------------------------------------------------------------
__global__ void detect_mask_kernel(const unsigned char* __restrict__ m) {
    __shared__ int nz[4];
    if (threadIdx.x < 4) nz[threadIdx.x] = 0;
    __syncthreads();
    int loc = 0;
    for (int i = threadIdx.x; i < 8192; i += blockDim.x)
        if (m[i]) loc = 1;
    if (loc) atomicOr(&nz[threadIdx.x & 3], 1);
    __syncthreads();
    if (threadIdx.x == 0) {
        int mode;
        int tot = nz[0] | nz[1] | nz[2] | nz[3];
        if (!tot)                          mode = 0;
        else if (!(nz[1] | nz[2] | nz[3])) mode = 1; // int32 LE
        else if (!(nz[0] | nz[1]))         mode = 2; // float32 (0x3F800000)
        else                               mode = 0; // uint8/bool
        g_mask_mode = mode;
    }
}

// Convert mask (any dtype) into multiplicative float mask: 0 = masked, 1 = keep
__global__ void maskf_kernel(const void* __restrict__ m) {
    int i = blockIdx.x * blockDim.x + threadIdx.x;
    if (i >= BATCH * LKK) return;
    int mode = g_mask_mode;
    bool mm = (mode == 0) ? (((const unsigned char*)m)[i] != 0)
            : (mode == 1) ? (((const int*)m)[i] != 0)
                          : (((const float*)m)[i] != 0.f);
    g_maskf[i] = mm ? 0.f : 1.f;
}

// ---------------------------------------------------------------------------
// Fused weight transpose + fp16 convert for all 4 weights.
// ---------------------------------------------------------------------------
__global__ void wtrans4_kernel(const float* __restrict__ W0, __half* __restrict__ T0,
                               const float* __restrict__ W1, __half* __restrict__ T1,
                               const float* __restrict__ W2, __half* __restrict__ T2,
                               const float* __restrict__ W3, __half* __restrict__ T3) {
    const float* W = (blockIdx.z == 0) ? W0 : (blockIdx.z == 1) ? W1
                   : (blockIdx.z == 2) ? W2 : W3;
    __half* WT     = (blockIdx.z == 0) ? T0 : (blockIdx.z == 1) ? T1
                   : (blockIdx.z == 2) ? T2 : T3;
    __shared__ float t[32][33];
    int n0 = blockIdx.x * 32, k0 = blockIdx.y * 32;
    #pragma unroll
    for (int i = 0; i < 4; i++) {
        int k = threadIdx.y + i * 8;
        t[k][threadIdx.x] = W[(size_t)(k0 + k) * DMODEL + n0 + threadIdx.x];
    }
    __syncthreads();
    #pragma unroll
    for (int i = 0; i < 4; i++) {
        int n = threadIdx.y + i * 8;
        WT[(size_t)(n0 + n) * DMODEL + k0 + threadIdx.x] = __float2half(t[threadIdx.x][n]);
    }
}

// ---------------------------------------------------------------------------
// Warp-per-row fused LayerNorm for x and context. Output fp16.
// 8 warps per block, one 1024-float row per warp, shuffle-only reduction.
// ---------------------------------------------------------------------------
__global__ void ln2w_kernel(const float* __restrict__ x,
                            const float* __restrict__ ctx,
                            const float* __restrict__ wq_, const float* __restrict__ bq_,
                            const float* __restrict__ wc_, const float* __restrict__ bc_,
                            __half* __restrict__ oq_, __half* __restrict__ oc_) {
    int wid = threadIdx.x >> 5, lane = threadIdx.x & 31;
    int row = blockIdx.x * 8 + wid;
    bool isq = row < BATCH * LQQ;
    const float* src = isq ? x : ctx;
    const float* w   = isq ? wq_ : wc_;
    const float* bia = isq ? bq_ : bc_;
    __half* out      = isq ? oq_ : oc_;
    int r = isq ? row : row - BATCH * LQQ;

    const float4* xr = reinterpret_cast<const float4*>(src + (size_t)r * DMODEL);
    float4 xv[8];
    float s = 0.f, ss = 0.f;
    #pragma unroll
    for (int j = 0; j < 8; j++) {
        float4 a = xr[lane + j * 32];
        xv[j] = a;
        s  += a.x + a.y + a.z + a.w;
        ss += a.x * a.x + a.y * a.y + a.z * a.z + a.w * a.w;
    }
    #pragma unroll
    for (int o = 16; o; o >>= 1) {
        s  += __shfl_xor_sync(0xffffffffu, s,  o);
        ss += __shfl_xor_sync(0xffffffffu, ss, o);
    }
    float mean = s * (1.0f / DMODEL);
    float var  = ss * (1.0f / DMODEL) - mean * mean;
    float rstd = rsqrtf(var + 1e-5f);

    const float4* w4 = reinterpret_cast<const float4*>(w);
    const float4* b4 = reinterpret_cast<const float4*>(bia);
    __half* orow = out + (size_t)r * DMODEL;
    #pragma unroll
    for (int j = 0; j < 8; j++) {
        float4 wv = w4[lane + j * 32];
        float4 bv = b4[lane + j * 32];
        float4 a = xv[j];
        __half2 h0 = __floats2half2_rn((a.x - mean) * rstd * wv.x + bv.x,
                                       (a.y - mean) * rstd * wv.y + bv.y);
        __half2 h1 = __floats2half2_rn((a.z - mean) * rstd * wv.z + bv.z,
                                       (a.w - mean) * rstd * wv.w + bv.w);
        uint2 pk = make_uint2(*(unsigned*)&h0, *(unsigned*)&h1);
        *(uint2*)&orow[(lane + j * 32) * 4] = pk;
    }
}

// ---------------------------------------------------------------------------
// fp16 tensor-core GEMM core, cp.async 3-stage pipeline, ldmatrix loads.
// mode: 0 = half out, 1 = half transposed-per-head out (g_vt, smem-staged),
//       2 = float out.
// ---------------------------------------------------------------------------
#define TBM 128
#define TBN 128
#define TBK 32
#define KPAD 40
#define ROWB (KPAD * 2)
#define ASZH (TBM * KPAD)
#define STAGEB (ASZH * 2)

__device__ __forceinline__ void gemm_core(
        const __half* __restrict__ A,
        const __half* __restrict__ BT,
        void* __restrict__ Cout,
        int M, int N, int K, int mode, __half* gsm) {
    __half* As = gsm;
    __half* Bs = gsm + 3 * ASZH;

    int tid = threadIdx.x;
    int wid = tid >> 5, lane = tid & 31;
    int wm = wid >> 2, wn = wid & 3;
    int m0 = blockIdx.y * TBM, n0 = blockIdx.x * TBN;
    int tg = lane & 3;
    int lm = lane >> 3;
    int lr = lane & 7;

    float acc[4][4][4];
    #pragma unroll
    for (int i = 0; i < 4; i++)
        #pragma unroll
        for (int j = 0; j < 4; j++)
            #pragma unroll
            for (int t = 0; t < 4; t++) acc[i][j][t] = 0.f;

    auto load_tile = [&](int kt, int buf) {
        int k0 = kt * TBK;
        #pragma unroll
        for (int i = 0; i < 2; i++) {
            int cid = tid + i * 256;
            int row = cid >> 2, c8 = (cid & 3) * 8;
            cp_async16(&As[buf * ASZH + row * KPAD + c8],
                       A + (size_t)(m0 + row) * K + k0 + c8);
            cp_async16(&Bs[buf * ASZH + row * KPAD + c8],
                       BT + (size_t)(n0 + row) * K + k0 + c8);
        }
        cp_commit();
    };

    unsigned aoff = (unsigned)((wm * 64 + (lm & 1) * 8 + lr) * ROWB + (lm >> 1) * 16);
    unsigned boff = (unsigned)((wn * 32 + (lm >> 1) * 8 + lr) * ROWB + (lm & 1) * 16);

    unsigned aBase = smem_u32(As) + aoff;
    unsigned bBase = smem_u32(Bs) + boff;

    int nt = K / TBK;
    load_tile(0, 0);
    load_tile(1, 1);

    for (int kt = 0; kt < nt; kt++) {
        int cur = kt % 3;
        if (kt + 2 < nt) cp_wait<1>(); else cp_wait<0>();
        __syncthreads();
        if (kt + 2 < nt) load_tile(kt + 2, (kt + 2) % 3);

        unsigned aS = aBase + cur * STAGEB;
        unsigned bS = bBase + cur * STAGEB;

        #pragma unroll
        for (int ks = 0; ks < 2; ks++) {
            unsigned kofs = ks * 32;
            unsigned af[4][4];
            #pragma unroll
            for (int mf = 0; mf < 4; mf++)
                ldsm4(af[mf][0], af[mf][1], af[mf][2], af[mf][3],
                      aS + kofs + mf * 16 * ROWB);
            unsigned bf[4][2];
            #pragma unroll
            for (int g = 0; g < 2; g++)
                ldsm4(bf[g*2][0], bf[g*2][1], bf[g*2+1][0], bf[g*2+1][1],
                      bS + kofs + g * 16 * ROWB);
            #pragma unroll
            for (int mf = 0; mf < 4; mf++)
                #pragma unroll
                for (int nf = 0; nf < 4; nf++)
                    mma_f16(acc[mf][nf], af[mf][0], af[mf][1], af[mf][2], af[mf][3],
                            bf[nf][0], bf[nf][1]);
        }
    }

    if (mode == 1) {
        // Stage the tile into smem transposed ([n][m], stride 136), then
        // store coalesced 16B lines along kv into g_vt.
        __syncthreads();
        __half* ts = gsm;   // 128 * 136 halves = 34816 B < 61440 B available
        int rl = wm * 64 + (lane >> 2);
        int sc = wn * 32 + tg * 2;
        #pragma unroll
        for (int mf = 0; mf < 4; mf++) {
            #pragma unroll
            for (int nf = 0; nf < 4; nf++) {
                int r = rl + mf * 16;
                int c = sc + nf * 8;
                ts[c * 136 + r]           = __float2half(acc[mf][nf][0]);
                ts[(c + 1) * 136 + r]     = __float2half(acc[mf][nf][1]);
                ts[c * 136 + r + 8]       = __float2half(acc[mf][nf][2]);
                ts[(c + 1) * 136 + r + 8] = __float2half(acc[mf][nf][3]);
            }
        }
        __syncthreads();
        __half* vt = (__half*)Cout;
        int bb = m0 >> 11, kv0 = m0 & 2047;
        #pragma unroll
        for (int i = 0; i < 8; i++) {
            int id = tid + i * 256;
            int c = id >> 4, kv8 = (id & 15) * 8;
            *(uint4*)&vt[((size_t)(bb * 1024 + n0 + c)) * 2048 + kv0 + kv8] =
                *(const uint4*)&ts[c * 136 + kv8];
        }
        return;
    }

    int crow = m0 + wm * 64 + (lane >> 2);
    int ccol = n0 + wn * 32 + tg * 2;
    #pragma unroll
    for (int mf = 0; mf < 4; mf++) {
        #pragma unroll
        for (int nf = 0; nf < 4; nf++) {
            int r = crow + mf * 16;
            int c = ccol + nf * 8;
            float v0 = acc[mf][nf][0], v1 = acc[mf][nf][1];
            float v2 = acc[mf][nf][2], v3 = acc[mf][nf][3];
            if (mode == 0) {
                __half* Ch = (__half*)Cout;
                *(__half2*)&Ch[(size_t)r * N + c]       = __floats2half2_rn(v0, v1);
                *(__half2*)&Ch[(size_t)(r + 8) * N + c] = __floats2half2_rn(v2, v3);
            } else {
                float* Cf = (float*)Cout;
                *(float2*)&Cf[(size_t)r * N + c]       = make_float2(v0, v1);
                *(float2*)&Cf[(size_t)(r + 8) * N + c] = make_float2(v2, v3);
            }
        }
    }
}

__global__ __launch_bounds__(256, 2) void tgemm_kernel(
        const __half* __restrict__ A,
        const __half* __restrict__ BT,
        void* __restrict__ Cout,
        int M, int N, int K, int mode) {
    extern __shared__ __half gsm[];
    gemm_core(A, BT, Cout, M, N, K, mode, gsm);
}

__global__ __launch_bounds__(256, 2) void qkv3_kernel(
        const __half* __restrict__ qln,
        const __half* __restrict__ kvln,
        const __half* __restrict__ wq,
        const __half* __restrict__ wk,
        const __half* __restrict__ wv,
        __half* __restrict__ q,
        __half* __restrict__ k,
        __half* __restrict__ vt) {
    extern __shared__ __half gsm[];
    int z = blockIdx.z;
    const __half* A  = (z == 0) ? qln : kvln;
    const __half* BT = (z == 0) ? wq : (z == 1) ? wk : wv;
    void* C          = (z == 0) ? (void*)q : (z == 1) ? (void*)k : (void*)vt;
    int mode         = (z == 2) ? 1 : 0;
    gemm_core(A, BT, C, BATCH * LQQ, DMODEL, DMODEL, mode, gsm);
}

// ---------------------------------------------------------------------------
// Fused L2 norm over q and k: one warp per 64-half head vector.
// ---------------------------------------------------------------------------
__global__ void l2norm2_kernel(__half* __restrict__ q, __half* __restrict__ k, int nvec) {
    int idx  = blockIdx.x * blockDim.x + threadIdx.x;
    int warp = idx >> 5;
    int lane = idx & 31;
    if (warp >= 2 * nvec) return;
    __half* d = (warp < nvec) ? q : k;
    int w = (warp < nvec) ? warp : warp - nvec;
    __half2* p = reinterpret_cast<__half2*>(d) + (size_t)w * 32 + lane;
    float2 f = __half22float2(*p);
    float ss = f.x * f.x + f.y * f.y;
    #pragma unroll
    for (int o = 16; o; o >>= 1) ss += __shfl_xor_sync(0xffffffffu, ss, o);
    float sc = 1.0f / fmaxf(sqrtf(ss), 1e-12f);
    *p = __floats2half2_rn(f.x * sc, f.y * sc);
}

// ---------------------------------------------------------------------------
// Flash attention, fp16 mma + ldmatrix, fixed-max softmax via ex2.approx.
// 8 warps split on m only: warp tile 32 q-rows x 64 kv-cols.
// 128-key cp.async stages, two 64-key passes per barrier.
// ---------------------------------------------------------------------------
#define QROWS 256
#define QP 72
#define QROWB (QP * 2)
#define VP 136
#define VROWB (VP * 2)
#define KSTAGE (128 * QP * 2)
#define VSTAGE (64 * VP * 2)

__global__ __launch_bounds__(256) void attn_kernel(
        const __half* __restrict__ Q,
        const __half* __restrict__ Kp,
        const __half* __restrict__ Vt,
        const float* __restrict__ maskf,
        const float* __restrict__ tau_p,
        __half* __restrict__ O) {
    extern __shared__ __half smh[];
    __half* Qs = smh;                    // QROWS*QP
    __half* Ks = Qs + QROWS * QP;        // 2 * 128*QP
    __half* Vs = Ks + 2 * 128 * QP;      // 2 * 64*VP
    float*  Ms = (float*)(Vs + 2 * 64 * VP);  // 2 * 128

    int tid  = threadIdx.x;
    int wid  = tid >> 5, lane = tid & 31;
    int q0   = blockIdx.x * QROWS;
    int h    = blockIdx.y;
    int b    = blockIdx.z;
    int tg   = lane & 3;
    int lm   = lane >> 3;
    int lr   = lane & 7;

    float inv_tau = 1.0f / (*tau_p + 1e-6f);
    // exp(s*inv_tau - MFIX) = exp2(fma(s, c1, c2)); softmax is shift-invariant
    const float L2E = 1.44269504f;
    float c1 = inv_tau * L2E;
    float c2 = -fabsf(inv_tau) * L2E;

    const __half* Qbase = Q  + ((size_t)(b * LQQ + q0)) * DMODEL + h * DHEAD;
    const __half* Kbase = Kp + ((size_t)b * LKK) * DMODEL + h * DHEAD;
    const __half* Vbase = Vt + ((size_t)(b * 1024 + h * DHEAD)) * 2048;
    const float*  Mbase = maskf + (size_t)b * LKK;

    #pragma unroll
    for (int i = 0; i < 8; i++) {
        int cid = tid + i * 256;
        int r = cid >> 3, c8 = (cid & 7) * 8;
        cp_async16(&Qs[r * QP + c8], Qbase + (size_t)r * DMODEL + c8);
    }
    cp_commit();

    auto load_kv = [&](int k0, int buf) {
        #pragma unroll
        for (int i = 0; i < 4; i++) {
            int cid = tid + i * 256;
            int rk = cid >> 3, ck = (cid & 7) * 8;
            cp_async16(&Ks[buf * 128 * QP + rk * QP + ck],
                       Kbase + (size_t)(k0 + rk) * DMODEL + ck);
            int rv = cid >> 4, cv = (cid & 15) * 8;
            cp_async16(&Vs[buf * 64 * VP + rv * VP + cv],
                       Vbase + (size_t)rv * 2048 + k0 + cv);
        }
        if (tid < 32) cp_async16(&Ms[buf * 128 + tid * 4], Mbase + k0 + tid * 4);
        cp_commit();
    };

    load_kv(0, 0);

    float oacc[2][8][4];
    #pragma unroll
    for (int m = 0; m < 2; m++)
        #pragma unroll
        for (int i = 0; i < 8; i++)
            #pragma unroll
            for (int j = 0; j < 4; j++) oacc[m][i][j] = 0.f;
    float lsum[2][2] = {};

    unsigned aoff  = (unsigned)((wid * 32 + (lm & 1) * 8 + lr) * QROWB + (lm >> 1) * 16);
    unsigned boffK = (unsigned)(((lm >> 1) * 8 + lr) * QROWB + (lm & 1) * 16);
    unsigned boffV = (unsigned)(((lm >> 1) * 8 + lr) * VROWB + (lm & 1) * 16);
    unsigned qA = smem_u32(Qs) + aoff;
    unsigned kB = smem_u32(Ks) + boffK;
    unsigned vB = smem_u32(Vs) + boffV;

    const int NT = LKK / 128;
    for (int kt = 0; kt < NT; kt++) {
        int cur = kt & 1;
        cp_wait<0>();
        __syncthreads();
        if (kt + 1 < NT) load_kv((kt + 1) * 128, cur ^ 1);

        #pragma unroll
        for (int p = 0; p < 2; p++) {
            unsigned kS = kB + cur * KSTAGE + p * 64 * QROWB;
            unsigned vS = vB + cur * VSTAGE + p * 128;
            const float* Msb = Ms + cur * 128 + p * 64;

            float sacc[2][8][4];
            #pragma unroll
            for (int m = 0; m < 2; m++)
                #pragma unroll
                for (int i = 0; i < 8; i++)
                    #pragma unroll
                    for (int j = 0; j < 4; j++) sacc[m][i][j] = 0.f;

            #pragma unroll
            for (int ks = 0; ks < 4; ks++) {
                unsigned kofs = ks * 32;
                unsigned bf[8][2];
                #pragma unroll
                for (int g = 0; g < 4; g++)
                    ldsm4(bf[g*2][0], bf[g*2][1], bf[g*2+1][0], bf[g*2+1][1],
                          kS + kofs + g * 16 * QROWB);
                #pragma unroll
                for (int mf = 0; mf < 2; mf++) {
                    unsigned a0, a1, a2, a3;
                    ldsm4(a0, a1, a2, a3, qA + kofs + mf * 16 * QROWB);
                    #pragma unroll
                    for (int nf = 0; nf < 8; nf++)
                        mma_f16(sacc[mf][nf], a0, a1, a2, a3, bf[nf][0], bf[nf][1]);
                }
            }

            // mask multipliers depend only on nf: hoist as float2
            float2 mk2[8];
            #pragma unroll
            for (int nf = 0; nf < 8; nf++)
                mk2[nf] = *(const float2*)&Msb[nf * 8 + tg * 2];

            unsigned ph[2][8][2];
            #pragma unroll
            for (int mf = 0; mf < 2; mf++) {
                #pragma unroll
                for (int nf = 0; nf < 8; nf++) {
                    float p00 = ex2a(fmaf(sacc[mf][nf][0], c1, c2)) * mk2[nf].x;
                    float p01 = ex2a(fmaf(sacc[mf][nf][1], c1, c2)) * mk2[nf].y;
                    float p10 = ex2a(fmaf(sacc[mf][nf][2], c1, c2)) * mk2[nf].x;
                    float p11 = ex2a(fmaf(sacc[mf][nf][3], c1, c2)) * mk2[nf].y;
                    lsum[mf][0] += p00 + p01;
                    lsum[mf][1] += p10 + p11;
                    ph[mf][nf][0] = packh2(p00, p01);
                    ph[mf][nf][1] = packh2(p10, p11);
                }
            }

            #pragma unroll
            for (int ks = 0; ks < 4; ks++) {
                unsigned kofs = ks * 32;
                unsigned bf[8][2];
                #pragma unroll
                for (int g = 0; g < 4; g++)
                    ldsm4(bf[g*2][0], bf[g*2][1], bf[g*2+1][0], bf[g*2+1][1],
                          vS + kofs + g * 16 * VROWB);
                #pragma unroll
                for (int mf = 0; mf < 2; mf++) {
                    unsigned a0 = ph[mf][2*ks][0];
                    unsigned a1 = ph[mf][2*ks][1];
                    unsigned a2 = ph[mf][2*ks+1][0];
                    unsigned a3 = ph[mf][2*ks+1][1];
                    #pragma unroll
                    for (int nf = 0; nf < 8; nf++)
                        mma_f16(oacc[mf][nf], a0, a1, a2, a3, bf[nf][0], bf[nf][1]);
                }
            }
        }
    }

    #pragma unroll
    for (int mf = 0; mf < 2; mf++) {
        lsum[mf][0] += __shfl_xor_sync(0xffffffffu, lsum[mf][0], 1);
        lsum[mf][0] += __shfl_xor_sync(0xffffffffu, lsum[mf][0], 2);
        lsum[mf][1] += __shfl_xor_sync(0xffffffffu, lsum[mf][1], 1);
        lsum[mf][1] += __shfl_xor_sync(0xffffffffu, lsum[mf][1], 2);
    }

    int rA = wid * 32 + (lane >> 2);
    #pragma unroll
    for (int mf = 0; mf < 2; mf++) {
        int r0 = rA + mf * 16;
        float li0 = 1.0f / lsum[mf][0];
        float li1 = 1.0f / lsum[mf][1];
        int gcol = h * DHEAD + tg * 2;
        #pragma unroll
        for (int nf = 0; nf < 8; nf++) {
            size_t base0 = ((size_t)(b * LQQ + q0 + r0)) * DMODEL + gcol + nf * 8;
            size_t base1 = ((size_t)(b * LQQ + q0 + r0 + 8)) * DMODEL + gcol + nf * 8;
            *(__half2*)&O[base0] = __floats2half2_rn(oacc[mf][nf][0] * li0,
                                                     oacc[mf][nf][1] * li0);
            *(__half2*)&O[base1] = __floats2half2_rn(oacc[mf][nf][2] * li1,
                                                     oacc[mf][nf][3] * li1);
        }
    }
}

// ---------------------------------------------------------------------------
// Launcher
// ---------------------------------------------------------------------------
extern "C" void kernel_launch(void* const* d_in, const int* in_sizes, int n_in,
                              void* d_out, int out_size) {
    const float* x     = (const float*)d_in[0];
    const float* ctx   = (const float*)d_in[1];
    const void*  mask  = d_in[2];
    const float* lnqw  = (const float*)d_in[3];
    const float* lnqb  = (const float*)d_in[4];
    const float* lncw  = (const float*)d_in[5];
    const float* lncb  = (const float*)d_in[6];
    const float* Wq    = (const float*)d_in[7];
    const float* Wk    = (const float*)d_in[8];
    const float* Wv    = (const float*)d_in[9];
    const float* Wo    = (const float*)d_in[10];
    const float* taup  = (const float*)d_in[11];
    float* out = (float*)d_out;

    __half *qln, *kvln, *q, *k, *vt, *ao, *wq, *wk, *wv, *wo;
    float *maskf;
    cudaGetSymbolAddress((void**)&qln,   g_qln);
    cudaGetSymbolAddress((void**)&kvln,  g_kvln);
    cudaGetSymbolAddress((void**)&q,     g_q);
    cudaGetSymbolAddress((void**)&k,     g_k);
    cudaGetSymbolAddress((void**)&vt,    g_vt);
    cudaGetSymbolAddress((void**)&ao,    g_ao);
    cudaGetSymbolAddress((void**)&maskf, g_maskf);
    cudaGetSymbolAddress((void**)&wq,    g_wq);
    cudaGetSymbolAddress((void**)&wk,    g_wk);
    cudaGetSymbolAddress((void**)&wv,    g_wv);
    cudaGetSymbolAddress((void**)&wo,    g_wo);

    const int smem_gemm = (int)(6 * ASZH * sizeof(__half));
    cudaFuncSetAttribute(tgemm_kernel, cudaFuncAttributeMaxDynamicSharedMemorySize, smem_gemm);
    cudaFuncSetAttribute(qkv3_kernel,  cudaFuncAttributeMaxDynamicSharedMemorySize, smem_gemm);

    const int smem_attn = (int)((QROWS * QP + 2 * 128 * QP + 2 * 64 * VP) * sizeof(__half)
                              + 2 * 128 * sizeof(float));
    cudaFuncSetAttribute(attn_kernel, cudaFuncAttributeMaxDynamicSharedMemorySize, smem_attn);

    detect_mask_kernel<<<1, 256>>>((const unsigned char*)mask);
    maskf_kernel<<<(BATCH * LKK + 255) / 256, 256>>>(mask);

    dim3 wtb(32, 8), wtg(DMODEL / 32, DMODEL / 32, 4);
    wtrans4_kernel<<<wtg, wtb>>>(Wq, wq, Wk, wk, Wv, wv, Wo, wo);

    ln2w_kernel<<<BATCH * (LQQ + LKK) / 8, 256>>>(x, ctx, lnqw, lnqb, lncw, lncb, qln, kvln);

    dim3 gqkv(DMODEL / TBN, (BATCH * LQQ) / TBM, 3);
    qkv3_kernel<<<gqkv, 256, smem_gemm>>>(qln, kvln, wq, wk, wv, q, k, vt);

    int nvec = BATCH * LQQ * NHEAD;
    l2norm2_kernel<<<(2 * nvec * 32) / 256, 256>>>(q, k, nvec);

    attn_kernel<<<dim3(LQQ / QROWS, NHEAD, BATCH), 256, smem_attn>>>(q, k, vt, maskf, taup, ao);

    dim3 gg(DMODEL / TBN, (BATCH * LQQ) / TBM);
    tgemm_kernel<<<gg, 256, smem_gemm>>>(ao, wo, out, BATCH * LQQ, DMODEL, DMODEL, 2);
}

// round 16
// speedup vs baseline: 1.1232x; 1.0415x over previous
#include <cuda_runtime.h>
#include <cuda_fp16.h>
#include <math.h>

// Problem constants
#define BATCH 4
#define LQQ   2048
#define LKK   2048
#define DMODEL 1024
#define NHEAD 16
#define DHEAD 64

// Scratch (static device arrays -- no runtime allocation allowed)
__device__ __half g_qln [BATCH * LQQ * DMODEL];
__device__ __half g_kvln[BATCH * LKK * DMODEL];
__device__ __half g_q   [BATCH * LQQ * DMODEL];
__device__ __half g_k   [BATCH * LKK * DMODEL];
__device__ __half g_vt  [BATCH * NHEAD * DHEAD * LKK];  // [b][h][d][kv]
__device__ __half g_ao  [BATCH * LQQ * DMODEL];
__device__ __half g_wq  [DMODEL * DMODEL];  // transposed [N][K]
__device__ __half g_wk  [DMODEL * DMODEL];
__device__ __half g_wv  [DMODEL * DMODEL];
__device__ __half g_wo  [DMODEL * DMODEL];
__device__ float  g_maskf[BATCH * LKK];   // 0.0 = masked, 1.0 = keep

// ---------------------------------------------------------------------------
// mma / cp.async / ldmatrix helpers
// ---------------------------------------------------------------------------
__device__ __forceinline__ void mma_f16(float c[4],
                                        unsigned a0, unsigned a1, unsigned a2, unsigned a3,
                                        unsigned b0, unsigned b1) {
    asm volatile(
        "mma.sync.aligned.m16n8k16.row.col.f32.f16.f16.f32 "
        "{%0,%1,%2,%3},{%4,%5,%6,%7},{%8,%9},{%0,%1,%2,%3};"
        : "+f"(c[0]), "+f"(c[1]), "+f"(c[2]), "+f"(c[3])
        : "r"(a0), "r"(a1), "r"(a2), "r"(a3), "r"(b0), "r"(b1));
}

__device__ __forceinline__ void cp_async16(void* smem_dst, const void* gmem_src) {
    unsigned sa = (unsigned)__cvta_generic_to_shared(smem_dst);
    asm volatile("cp.async.cg.shared.global [%0], [%1], 16;" :: "r"(sa), "l"(gmem_src));
}
__device__ __forceinline__ void cp_commit() {
    asm volatile("cp.async.commit_group;");
}
template <int N>
__device__ __forceinline__ void cp_wait() {
    asm volatile("cp.async.wait_group %0;" :: "n"(N));
}

__device__ __forceinline__ unsigned smem_u32(const void* p) {
    return (unsigned)__cvta_generic_to_shared(p);
}
__device__ __forceinline__ void ldsm4(unsigned& d0, unsigned& d1,
                                      unsigned& d2, unsigned& d3, unsigned saddr) {
    asm volatile("ldmatrix.sync.aligned.m8n8.x4.shared.b16 {%0,%1,%2,%3}, [%4];"
                 : "=r"(d0), "=r"(d1), "=r"(d2), "=r"(d3) : "r"(saddr));
}
__device__ __forceinline__ unsigned packh2(float a, float b) {
    __half2 h = __floats2half2_rn(a, b);
    return *(unsigned*)&h;
}
__device__ __forceinline__ float ex2a(float x) {
    float y;
    asm("ex2.approx.f32 %0, %1;" : "=f"(y) : "f"(x));
    return y;
}

// ---------------------------------------------------------------------------
// Mask -> multiplicative float mask with per-block dtype self-detection.
// Each block scans the first 8192 bytes (full u8 coverage; enough sample for
// i32/f32 at 10% density) and derives the dtype locally, then converts its
// slice. One launch, no global mode state.
// ---------------------------------------------------------------------------
__global__ void maskf_kernel(const void* __restrict__ m) {
    __shared__ int nz[4];
    if (threadIdx.x < 4) nz[threadIdx.x] = 0;
    __syncthreads();
    const unsigned char* m8 = (const unsigned char*)m;
    int loc[4] = {0, 0, 0, 0};
    for (int i = threadIdx.x; i < 8192; i += blockDim.x)
        if (m8[i]) loc[i & 3] = 1;
    if (loc[0] | loc[1] | loc[2] | loc[3]) {
        if (loc[0]) atomicOr(&nz[0], 1);
        if (loc[1]) atomicOr(&nz[1], 1);
        if (loc[2]) atomicOr(&nz[2], 1);
        if (loc[3]) atomicOr(&nz[3], 1);
    }
    __syncthreads();
    int mode;
    int tot = nz[0] | nz[1] | nz[2] | nz[3];
    if (!tot)                          mode = 0;
    else if (!(nz[1] | nz[2] | nz[3])) mode = 1; // int32 LE
    else if (!(nz[0] | nz[1]))         mode = 2; // float32 (0x3F800000)
    else                               mode = 0; // uint8/bool

    int i = blockIdx.x * blockDim.x + threadIdx.x;
    if (i >= BATCH * LKK) return;
    bool mm = (mode == 0) ? (m8[i] != 0)
            : (mode == 1) ? (((const int*)m)[i] != 0)
                          : (((const float*)m)[i] != 0.f);
    g_maskf[i] = mm ? 0.f : 1.f;
}

// ---------------------------------------------------------------------------
// Fused weight transpose + fp16 convert for all 4 weights.
// ---------------------------------------------------------------------------
__global__ void wtrans4_kernel(const float* __restrict__ W0, __half* __restrict__ T0,
                               const float* __restrict__ W1, __half* __restrict__ T1,
                               const float* __restrict__ W2, __half* __restrict__ T2,
                               const float* __restrict__ W3, __half* __restrict__ T3) {
    const float* W = (blockIdx.z == 0) ? W0 : (blockIdx.z == 1) ? W1
                   : (blockIdx.z == 2) ? W2 : W3;
    __half* WT     = (blockIdx.z == 0) ? T0 : (blockIdx.z == 1) ? T1
                   : (blockIdx.z == 2) ? T2 : T3;
    __shared__ float t[32][33];
    int n0 = blockIdx.x * 32, k0 = blockIdx.y * 32;
    #pragma unroll
    for (int i = 0; i < 4; i++) {
        int k = threadIdx.y + i * 8;
        t[k][threadIdx.x] = W[(size_t)(k0 + k) * DMODEL + n0 + threadIdx.x];
    }
    __syncthreads();
    #pragma unroll
    for (int i = 0; i < 4; i++) {
        int n = threadIdx.y + i * 8;
        WT[(size_t)(n0 + n) * DMODEL + k0 + threadIdx.x] = __float2half(t[threadIdx.x][n]);
    }
}

// ---------------------------------------------------------------------------
// Warp-per-row fused LayerNorm for x and context. Output fp16.
// ---------------------------------------------------------------------------
__global__ void ln2w_kernel(const float* __restrict__ x,
                            const float* __restrict__ ctx,
                            const float* __restrict__ wq_, const float* __restrict__ bq_,
                            const float* __restrict__ wc_, const float* __restrict__ bc_,
                            __half* __restrict__ oq_, __half* __restrict__ oc_) {
    int wid = threadIdx.x >> 5, lane = threadIdx.x & 31;
    int row = blockIdx.x * 8 + wid;
    bool isq = row < BATCH * LQQ;
    const float* src = isq ? x : ctx;
    const float* w   = isq ? wq_ : wc_;
    const float* bia = isq ? bq_ : bc_;
    __half* out      = isq ? oq_ : oc_;
    int r = isq ? row : row - BATCH * LQQ;

    const float4* xr = reinterpret_cast<const float4*>(src + (size_t)r * DMODEL);
    float4 xv[8];
    float s = 0.f, ss = 0.f;
    #pragma unroll
    for (int j = 0; j < 8; j++) {
        float4 a = xr[lane + j * 32];
        xv[j] = a;
        s  += a.x + a.y + a.z + a.w;
        ss += a.x * a.x + a.y * a.y + a.z * a.z + a.w * a.w;
    }
    #pragma unroll
    for (int o = 16; o; o >>= 1) {
        s  += __shfl_xor_sync(0xffffffffu, s,  o);
        ss += __shfl_xor_sync(0xffffffffu, ss, o);
    }
    float mean = s * (1.0f / DMODEL);
    float var  = ss * (1.0f / DMODEL) - mean * mean;
    float rstd = rsqrtf(var + 1e-5f);

    const float4* w4 = reinterpret_cast<const float4*>(w);
    const float4* b4 = reinterpret_cast<const float4*>(bia);
    __half* orow = out + (size_t)r * DMODEL;
    #pragma unroll
    for (int j = 0; j < 8; j++) {
        float4 wv = w4[lane + j * 32];
        float4 bv = b4[lane + j * 32];
        float4 a = xv[j];
        __half2 h0 = __floats2half2_rn((a.x - mean) * rstd * wv.x + bv.x,
                                       (a.y - mean) * rstd * wv.y + bv.y);
        __half2 h1 = __floats2half2_rn((a.z - mean) * rstd * wv.z + bv.z,
                                       (a.w - mean) * rstd * wv.w + bv.w);
        uint2 pk = make_uint2(*(unsigned*)&h0, *(unsigned*)&h1);
        *(uint2*)&orow[(lane + j * 32) * 4] = pk;
    }
}

// ---------------------------------------------------------------------------
// fp16 tensor-core GEMM core, cp.async 3-stage pipeline, ldmatrix loads.
// mode: 0 = half out, 1 = half transposed-per-head out (g_vt, smem-staged),
//       2 = float out, 3 = half out with per-64-col-head L2 normalization.
// ---------------------------------------------------------------------------
#define TBM 128
#define TBN 128
#define TBK 32
#define KPAD 40
#define ROWB (KPAD * 2)
#define ASZH (TBM * KPAD)
#define STAGEB (ASZH * 2)

__device__ __forceinline__ void gemm_core(
        const __half* __restrict__ A,
        const __half* __restrict__ BT,
        void* __restrict__ Cout,
        int M, int N, int K, int mode, __half* gsm) {
    __half* As = gsm;
    __half* Bs = gsm + 3 * ASZH;

    int tid = threadIdx.x;
    int wid = tid >> 5, lane = tid & 31;
    int wm = wid >> 2, wn = wid & 3;
    int m0 = blockIdx.y * TBM, n0 = blockIdx.x * TBN;
    int tg = lane & 3;
    int lm = lane >> 3;
    int lr = lane & 7;

    float acc[4][4][4];
    #pragma unroll
    for (int i = 0; i < 4; i++)
        #pragma unroll
        for (int j = 0; j < 4; j++)
            #pragma unroll
            for (int t = 0; t < 4; t++) acc[i][j][t] = 0.f;

    auto load_tile = [&](int kt, int buf) {
        int k0 = kt * TBK;
        #pragma unroll
        for (int i = 0; i < 2; i++) {
            int cid = tid + i * 256;
            int row = cid >> 2, c8 = (cid & 3) * 8;
            cp_async16(&As[buf * ASZH + row * KPAD + c8],
                       A + (size_t)(m0 + row) * K + k0 + c8);
            cp_async16(&Bs[buf * ASZH + row * KPAD + c8],
                       BT + (size_t)(n0 + row) * K + k0 + c8);
        }
        cp_commit();
    };

    unsigned aoff = (unsigned)((wm * 64 + (lm & 1) * 8 + lr) * ROWB + (lm >> 1) * 16);
    unsigned boff = (unsigned)((wn * 32 + (lm >> 1) * 8 + lr) * ROWB + (lm & 1) * 16);

    unsigned aBase = smem_u32(As) + aoff;
    unsigned bBase = smem_u32(Bs) + boff;

    int nt = K / TBK;
    load_tile(0, 0);
    load_tile(1, 1);

    for (int kt = 0; kt < nt; kt++) {
        int cur = kt % 3;
        if (kt + 2 < nt) cp_wait<1>(); else cp_wait<0>();
        __syncthreads();
        if (kt + 2 < nt) load_tile(kt + 2, (kt + 2) % 3);

        unsigned aS = aBase + cur * STAGEB;
        unsigned bS = bBase + cur * STAGEB;

        #pragma unroll
        for (int ks = 0; ks < 2; ks++) {
            unsigned kofs = ks * 32;
            unsigned af[4][4];
            #pragma unroll
            for (int mf = 0; mf < 4; mf++)
                ldsm4(af[mf][0], af[mf][1], af[mf][2], af[mf][3],
                      aS + kofs + mf * 16 * ROWB);
            unsigned bf[4][2];
            #pragma unroll
            for (int g = 0; g < 2; g++)
                ldsm4(bf[g*2][0], bf[g*2][1], bf[g*2+1][0], bf[g*2+1][1],
                      bS + kofs + g * 16 * ROWB);
            #pragma unroll
            for (int mf = 0; mf < 4; mf++)
                #pragma unroll
                for (int nf = 0; nf < 4; nf++)
                    mma_f16(acc[mf][nf], af[mf][0], af[mf][1], af[mf][2], af[mf][3],
                            bf[nf][0], bf[nf][1]);
        }
    }

    if (mode == 1) {
        // Stage the tile into smem transposed ([n][m], stride 136), then
        // store coalesced 16B lines along kv into g_vt.
        __syncthreads();
        __half* ts = gsm;
        int rl = wm * 64 + (lane >> 2);
        int sc = wn * 32 + tg * 2;
        #pragma unroll
        for (int mf = 0; mf < 4; mf++) {
            #pragma unroll
            for (int nf = 0; nf < 4; nf++) {
                int r = rl + mf * 16;
                int c = sc + nf * 8;
                ts[c * 136 + r]           = __float2half(acc[mf][nf][0]);
                ts[(c + 1) * 136 + r]     = __float2half(acc[mf][nf][1]);
                ts[c * 136 + r + 8]       = __float2half(acc[mf][nf][2]);
                ts[(c + 1) * 136 + r + 8] = __float2half(acc[mf][nf][3]);
            }
        }
        __syncthreads();
        __half* vt = (__half*)Cout;
        int bb = m0 >> 11, kv0 = m0 & 2047;
        #pragma unroll
        for (int i = 0; i < 8; i++) {
            int id = tid + i * 256;
            int c = id >> 4, kv8 = (id & 15) * 8;
            *(uint4*)&vt[((size_t)(bb * 1024 + n0 + c)) * 2048 + kv0 + kv8] =
                *(const uint4*)&ts[c * 136 + kv8];
        }
        return;
    }

    float scl[4][2];   // per-row l2 scales for mode 3 (defaults unused)
    if (mode == 3) {
        // per-row, per-64-col-head sum of squares:
        // local 32-col partials, quad reduce, cross-warp pair via smem.
        float ssql[4][2];
        #pragma unroll
        for (int mf = 0; mf < 4; mf++) {
            float s0 = 0.f, s1 = 0.f;
            #pragma unroll
            for (int nf = 0; nf < 4; nf++) {
                s0 += acc[mf][nf][0] * acc[mf][nf][0] + acc[mf][nf][1] * acc[mf][nf][1];
                s1 += acc[mf][nf][2] * acc[mf][nf][2] + acc[mf][nf][3] * acc[mf][nf][3];
            }
            ssql[mf][0] = s0; ssql[mf][1] = s1;
        }
        #pragma unroll
        for (int mf = 0; mf < 4; mf++) {
            #pragma unroll
            for (int o = 1; o <= 2; o <<= 1) {
                ssql[mf][0] += __shfl_xor_sync(0xffffffffu, ssql[mf][0], o);
                ssql[mf][1] += __shfl_xor_sync(0xffffffffu, ssql[mf][1], o);
            }
        }
        __syncthreads();                 // mainloop smem reads complete
        float* ssqs = (float*)gsm;       // [128 rows][4 wn]
        int rl = wm * 64 + (lane >> 2);
        if (tg == 0) {
            #pragma unroll
            for (int mf = 0; mf < 4; mf++) {
                ssqs[(rl + mf * 16) * 4 + wn]     = ssql[mf][0];
                ssqs[(rl + mf * 16 + 8) * 4 + wn] = ssql[mf][1];
            }
        }
        __syncthreads();
        int hb = (wn >> 1) * 2;          // head base wn (0 or 2)
        #pragma unroll
        for (int mf = 0; mf < 4; mf++) {
            float t0 = ssqs[(rl + mf * 16) * 4 + hb]     + ssqs[(rl + mf * 16) * 4 + hb + 1];
            float t1 = ssqs[(rl + mf * 16 + 8) * 4 + hb] + ssqs[(rl + mf * 16 + 8) * 4 + hb + 1];
            scl[mf][0] = rsqrtf(fmaxf(t0, 1e-24f));
            scl[mf][1] = rsqrtf(fmaxf(t1, 1e-24f));
        }
    }

    int crow = m0 + wm * 64 + (lane >> 2);
    int ccol = n0 + wn * 32 + tg * 2;
    #pragma unroll
    for (int mf = 0; mf < 4; mf++) {
        #pragma unroll
        for (int nf = 0; nf < 4; nf++) {
            int r = crow + mf * 16;
            int c = ccol + nf * 8;
            float v0 = acc[mf][nf][0], v1 = acc[mf][nf][1];
            float v2 = acc[mf][nf][2], v3 = acc[mf][nf][3];
            if (mode == 2) {
                float* Cf = (float*)Cout;
                *(float2*)&Cf[(size_t)r * N + c]       = make_float2(v0, v1);
                *(float2*)&Cf[(size_t)(r + 8) * N + c] = make_float2(v2, v3);
            } else {
                if (mode == 3) {
                    v0 *= scl[mf][0]; v1 *= scl[mf][0];
                    v2 *= scl[mf][1]; v3 *= scl[mf][1];
                }
                __half* Ch = (__half*)Cout;
                *(__half2*)&Ch[(size_t)r * N + c]       = __floats2half2_rn(v0, v1);
                *(__half2*)&Ch[(size_t)(r + 8) * N + c] = __floats2half2_rn(v2, v3);
            }
        }
    }
}

__global__ __launch_bounds__(256, 2) void tgemm_kernel(
        const __half* __restrict__ A,
        const __half* __restrict__ BT,
        void* __restrict__ Cout,
        int M, int N, int K, int mode) {
    extern __shared__ __half gsm[];
    gemm_core(A, BT, Cout, M, N, K, mode, gsm);
}

__global__ __launch_bounds__(256, 2) void qkv3_kernel(
        const __half* __restrict__ qln,
        const __half* __restrict__ kvln,
        const __half* __restrict__ wq,
        const __half* __restrict__ wk,
        const __half* __restrict__ wv,
        __half* __restrict__ q,
        __half* __restrict__ k,
        __half* __restrict__ vt) {
    extern __shared__ __half gsm[];
    int z = blockIdx.z;
    const __half* A  = (z == 0) ? qln : kvln;
    const __half* BT = (z == 0) ? wq : (z == 1) ? wk : wv;
    void* C          = (z == 0) ? (void*)q : (z == 1) ? (void*)k : (void*)vt;
    int mode         = (z == 2) ? 1 : 3;   // q,k: fused per-head l2norm
    gemm_core(A, BT, C, BATCH * LQQ, DMODEL, DMODEL, mode, gsm);
}

// ---------------------------------------------------------------------------
// Flash attention, fp16 mma + ldmatrix, fixed-max softmax via ex2.approx.
// 8 warps split on m only: warp tile 32 q-rows x 64 kv-cols.
// 128-key cp.async stages, two 64-key passes per barrier.
// ---------------------------------------------------------------------------
#define QROWS 256
#define QP 72
#define QROWB (QP * 2)
#define VP 136
#define VROWB (VP * 2)
#define KSTAGE (128 * QP * 2)
#define VSTAGE (64 * VP * 2)

__global__ __launch_bounds__(256) void attn_kernel(
        const __half* __restrict__ Q,
        const __half* __restrict__ Kp,
        const __half* __restrict__ Vt,
        const float* __restrict__ maskf,
        const float* __restrict__ tau_p,
        __half* __restrict__ O) {
    extern __shared__ __half smh[];
    __half* Qs = smh;                    // QROWS*QP
    __half* Ks = Qs + QROWS * QP;        // 2 * 128*QP
    __half* Vs = Ks + 2 * 128 * QP;      // 2 * 64*VP
    float*  Ms = (float*)(Vs + 2 * 64 * VP);  // 2 * 128

    int tid  = threadIdx.x;
    int wid  = tid >> 5, lane = tid & 31;
    int q0   = blockIdx.x * QROWS;
    int h    = blockIdx.y;
    int b    = blockIdx.z;
    int tg   = lane & 3;
    int lm   = lane >> 3;
    int lr   = lane & 7;

    float inv_tau = 1.0f / (*tau_p + 1e-6f);
    const float L2E = 1.44269504f;
    float c1 = inv_tau * L2E;
    float c2 = -fabsf(inv_tau) * L2E;

    const __half* Qbase = Q  + ((size_t)(b * LQQ + q0)) * DMODEL + h * DHEAD;
    const __half* Kbase = Kp + ((size_t)b * LKK) * DMODEL + h * DHEAD;
    const __half* Vbase = Vt + ((size_t)(b * 1024 + h * DHEAD)) * 2048;
    const float*  Mbase = maskf + (size_t)b * LKK;

    #pragma unroll
    for (int i = 0; i < 8; i++) {
        int cid = tid + i * 256;
        int r = cid >> 3, c8 = (cid & 7) * 8;
        cp_async16(&Qs[r * QP + c8], Qbase + (size_t)r * DMODEL + c8);
    }
    cp_commit();

    auto load_kv = [&](int k0, int buf) {
        #pragma unroll
        for (int i = 0; i < 4; i++) {
            int cid = tid + i * 256;
            int rk = cid >> 3, ck = (cid & 7) * 8;
            cp_async16(&Ks[buf * 128 * QP + rk * QP + ck],
                       Kbase + (size_t)(k0 + rk) * DMODEL + ck);
            int rv = cid >> 4, cv = (cid & 15) * 8;
            cp_async16(&Vs[buf * 64 * VP + rv * VP + cv],
                       Vbase + (size_t)rv * 2048 + k0 + cv);
        }
        if (tid < 32) cp_async16(&Ms[buf * 128 + tid * 4], Mbase + k0 + tid * 4);
        cp_commit();
    };

    load_kv(0, 0);

    float oacc[2][8][4];
    #pragma unroll
    for (int m = 0; m < 2; m++)
        #pragma unroll
        for (int i = 0; i < 8; i++)
            #pragma unroll
            for (int j = 0; j < 4; j++) oacc[m][i][j] = 0.f;
    float lsum[2][2] = {};

    unsigned aoff  = (unsigned)((wid * 32 + (lm & 1) * 8 + lr) * QROWB + (lm >> 1) * 16);
    unsigned boffK = (unsigned)(((lm >> 1) * 8 + lr) * QROWB + (lm & 1) * 16);
    unsigned boffV = (unsigned)(((lm >> 1) * 8 + lr) * VROWB + (lm & 1) * 16);
    unsigned qA = smem_u32(Qs) + aoff;
    unsigned kB = smem_u32(Ks) + boffK;
    unsigned vB = smem_u32(Vs) + boffV;

    const int NT = LKK / 128;
    for (int kt = 0; kt < NT; kt++) {
        int cur = kt & 1;
        cp_wait<0>();
        __syncthreads();
        if (kt + 1 < NT) load_kv((kt + 1) * 128, cur ^ 1);

        #pragma unroll
        for (int p = 0; p < 2; p++) {
            unsigned kS = kB + cur * KSTAGE + p * 64 * QROWB;
            unsigned vS = vB + cur * VSTAGE + p * 128;
            const float* Msb = Ms + cur * 128 + p * 64;

            float sacc[2][8][4];
            #pragma unroll
            for (int m = 0; m < 2; m++)
                #pragma unroll
                for (int i = 0; i < 8; i++)
                    #pragma unroll
                    for (int j = 0; j < 4; j++) sacc[m][i][j] = 0.f;

            #pragma unroll
            for (int ks = 0; ks < 4; ks++) {
                unsigned kofs = ks * 32;
                unsigned bf[8][2];
                #pragma unroll
                for (int g = 0; g < 4; g++)
                    ldsm4(bf[g*2][0], bf[g*2][1], bf[g*2+1][0], bf[g*2+1][1],
                          kS + kofs + g * 16 * QROWB);
                #pragma unroll
                for (int mf = 0; mf < 2; mf++) {
                    unsigned a0, a1, a2, a3;
                    ldsm4(a0, a1, a2, a3, qA + kofs + mf * 16 * QROWB);
                    #pragma unroll
                    for (int nf = 0; nf < 8; nf++)
                        mma_f16(sacc[mf][nf], a0, a1, a2, a3, bf[nf][0], bf[nf][1]);
                }
            }

            float2 mk2[8];
            #pragma unroll
            for (int nf = 0; nf < 8; nf++)
                mk2[nf] = *(const float2*)&Msb[nf * 8 + tg * 2];

            unsigned ph[2][8][2];
            #pragma unroll
            for (int mf = 0; mf < 2; mf++) {
                #pragma unroll
                for (int nf = 0; nf < 8; nf++) {
                    float p00 = ex2a(fmaf(sacc[mf][nf][0], c1, c2)) * mk2[nf].x;
                    float p01 = ex2a(fmaf(sacc[mf][nf][1], c1, c2)) * mk2[nf].y;
                    float p10 = ex2a(fmaf(sacc[mf][nf][2], c1, c2)) * mk2[nf].x;
                    float p11 = ex2a(fmaf(sacc[mf][nf][3], c1, c2)) * mk2[nf].y;
                    lsum[mf][0] += p00 + p01;
                    lsum[mf][1] += p10 + p11;
                    ph[mf][nf][0] = packh2(p00, p01);
                    ph[mf][nf][1] = packh2(p10, p11);
                }
            }

            #pragma unroll
            for (int ks = 0; ks < 4; ks++) {
                unsigned kofs = ks * 32;
                unsigned bf[8][2];
                #pragma unroll
                for (int g = 0; g < 4; g++)
                    ldsm4(bf[g*2][0], bf[g*2][1], bf[g*2+1][0], bf[g*2+1][1],
                          vS + kofs + g * 16 * VROWB);
                #pragma unroll
                for (int mf = 0; mf < 2; mf++) {
                    unsigned a0 = ph[mf][2*ks][0];
                    unsigned a1 = ph[mf][2*ks][1];
                    unsigned a2 = ph[mf][2*ks+1][0];
                    unsigned a3 = ph[mf][2*ks+1][1];
                    #pragma unroll
                    for (int nf = 0; nf < 8; nf++)
                        mma_f16(oacc[mf][nf], a0, a1, a2, a3, bf[nf][0], bf[nf][1]);
                }
            }
        }
    }

    #pragma unroll
    for (int mf = 0; mf < 2; mf++) {
        lsum[mf][0] += __shfl_xor_sync(0xffffffffu, lsum[mf][0], 1);
        lsum[mf][0] += __shfl_xor_sync(0xffffffffu, lsum[mf][0], 2);
        lsum[mf][1] += __shfl_xor_sync(0xffffffffu, lsum[mf][1], 1);
        lsum[mf][1] += __shfl_xor_sync(0xffffffffu, lsum[mf][1], 2);
    }

    int rA = wid * 32 + (lane >> 2);
    #pragma unroll
    for (int mf = 0; mf < 2; mf++) {
        int r0 = rA + mf * 16;
        float li0 = 1.0f / lsum[mf][0];
        float li1 = 1.0f / lsum[mf][1];
        int gcol = h * DHEAD + tg * 2;
        #pragma unroll
        for (int nf = 0; nf < 8; nf++) {
            size_t base0 = ((size_t)(b * LQQ + q0 + r0)) * DMODEL + gcol + nf * 8;
            size_t base1 = ((size_t)(b * LQQ + q0 + r0 + 8)) * DMODEL + gcol + nf * 8;
            *(__half2*)&O[base0] = __floats2half2_rn(oacc[mf][nf][0] * li0,
                                                     oacc[mf][nf][1] * li0);
            *(__half2*)&O[base1] = __floats2half2_rn(oacc[mf][nf][2] * li1,
                                                     oacc[mf][nf][3] * li1);
        }
    }
}

// ---------------------------------------------------------------------------
// Launcher
// ---------------------------------------------------------------------------
extern "C" void kernel_launch(void* const* d_in, const int* in_sizes, int n_in,
                              void* d_out, int out_size) {
    const float* x     = (const float*)d_in[0];
    const float* ctx   = (const float*)d_in[1];
    const void*  mask  = d_in[2];
    const float* lnqw  = (const float*)d_in[3];
    const float* lnqb  = (const float*)d_in[4];
    const float* lncw  = (const float*)d_in[5];
    const float* lncb  = (const float*)d_in[6];
    const float* Wq    = (const float*)d_in[7];
    const float* Wk    = (const float*)d_in[8];
    const float* Wv    = (const float*)d_in[9];
    const float* Wo    = (const float*)d_in[10];
    const float* taup  = (const float*)d_in[11];
    float* out = (float*)d_out;

    __half *qln, *kvln, *q, *k, *vt, *ao, *wq, *wk, *wv, *wo;
    float *maskf;
    cudaGetSymbolAddress((void**)&qln,   g_qln);
    cudaGetSymbolAddress((void**)&kvln,  g_kvln);
    cudaGetSymbolAddress((void**)&q,     g_q);
    cudaGetSymbolAddress((void**)&k,     g_k);
    cudaGetSymbolAddress((void**)&vt,    g_vt);
    cudaGetSymbolAddress((void**)&ao,    g_ao);
    cudaGetSymbolAddress((void**)&maskf, g_maskf);
    cudaGetSymbolAddress((void**)&wq,    g_wq);
    cudaGetSymbolAddress((void**)&wk,    g_wk);
    cudaGetSymbolAddress((void**)&wv,    g_wv);
    cudaGetSymbolAddress((void**)&wo,    g_wo);

    const int smem_gemm = (int)(6 * ASZH * sizeof(__half));
    cudaFuncSetAttribute(tgemm_kernel, cudaFuncAttributeMaxDynamicSharedMemorySize, smem_gemm);
    cudaFuncSetAttribute(qkv3_kernel,  cudaFuncAttributeMaxDynamicSharedMemorySize, smem_gemm);

    const int smem_attn = (int)((QROWS * QP + 2 * 128 * QP + 2 * 64 * VP) * sizeof(__half)
                              + 2 * 128 * sizeof(float));
    cudaFuncSetAttribute(attn_kernel, cudaFuncAttributeMaxDynamicSharedMemorySize, smem_attn);

    maskf_kernel<<<(BATCH * LKK + 255) / 256, 256>>>(mask);

    dim3 wtb(32, 8), wtg(DMODEL / 32, DMODEL / 32, 4);
    wtrans4_kernel<<<wtg, wtb>>>(Wq, wq, Wk, wk, Wv, wv, Wo, wo);

    ln2w_kernel<<<BATCH * (LQQ + LKK) / 8, 256>>>(x, ctx, lnqw, lnqb, lncw, lncb, qln, kvln);

    // fused Q/K/V projections; q,k l2-normalized in the epilogue (mode 3)
    dim3 gqkv(DMODEL / TBN, (BATCH * LQQ) / TBM, 3);
    qkv3_kernel<<<gqkv, 256, smem_gemm>>>(qln, kvln, wq, wk, wv, q, k, vt);

    attn_kernel<<<dim3(LQQ / QROWS, NHEAD, BATCH), 256, smem_attn>>>(q, k, vt, maskf, taup, ao);

    dim3 gg(DMODEL / TBN, (BATCH * LQQ) / TBM);
    tgemm_kernel<<<gg, 256, smem_gemm>>>(ao, wo, out, BATCH * LQQ, DMODEL, DMODEL, 2);
}

// round 17
// speedup vs baseline: 1.1326x; 1.0084x over previous
#include <cuda_runtime.h>
#include <cuda_fp16.h>
#include <math.h>

// Problem constants
#define BATCH 4
#define LQQ   2048
#define LKK   2048
#define DMODEL 1024
#define NHEAD 16
#define DHEAD 64

// Scratch (static device arrays -- no runtime allocation allowed)
__device__ __half g_qln [BATCH * LQQ * DMODEL];
__device__ __half g_kvln[BATCH * LKK * DMODEL];
__device__ __half g_q   [BATCH * LQQ * DMODEL];
__device__ __half g_k   [BATCH * LKK * DMODEL];
__device__ __half g_vt  [BATCH * NHEAD * DHEAD * LKK];  // [b][h][d][kv]
__device__ __half g_ao  [BATCH * LQQ * DMODEL];
__device__ __half g_wq  [DMODEL * DMODEL];  // transposed [N][K]
__device__ __half g_wk  [DMODEL * DMODEL];
__device__ __half g_wv  [DMODEL * DMODEL];
__device__ __half g_wo  [DMODEL * DMODEL];
__device__ float  g_maskf[BATCH * LKK];   // 0.0 = masked, 1.0 = keep

// ---------------------------------------------------------------------------
// mma / cp.async / ldmatrix helpers
// ---------------------------------------------------------------------------
__device__ __forceinline__ void mma_f16(float c[4],
                                        unsigned a0, unsigned a1, unsigned a2, unsigned a3,
                                        unsigned b0, unsigned b1) {
    asm volatile(
        "mma.sync.aligned.m16n8k16.row.col.f32.f16.f16.f32 "
        "{%0,%1,%2,%3},{%4,%5,%6,%7},{%8,%9},{%0,%1,%2,%3};"
        : "+f"(c[0]), "+f"(c[1]), "+f"(c[2]), "+f"(c[3])
        : "r"(a0), "r"(a1), "r"(a2), "r"(a3), "r"(b0), "r"(b1));
}

__device__ __forceinline__ void cp_async16(void* smem_dst, const void* gmem_src) {
    unsigned sa = (unsigned)__cvta_generic_to_shared(smem_dst);
    asm volatile("cp.async.cg.shared.global [%0], [%1], 16;" :: "r"(sa), "l"(gmem_src));
}
__device__ __forceinline__ void cp_commit() {
    asm volatile("cp.async.commit_group;");
}
template <int N>
__device__ __forceinline__ void cp_wait() {
    asm volatile("cp.async.wait_group %0;" :: "n"(N));
}

__device__ __forceinline__ unsigned smem_u32(const void* p) {
    return (unsigned)__cvta_generic_to_shared(p);
}
__device__ __forceinline__ void ldsm4(unsigned& d0, unsigned& d1,
                                      unsigned& d2, unsigned& d3, unsigned saddr) {
    asm volatile("ldmatrix.sync.aligned.m8n8.x4.shared.b16 {%0,%1,%2,%3}, [%4];"
                 : "=r"(d0), "=r"(d1), "=r"(d2), "=r"(d3) : "r"(saddr));
}
__device__ __forceinline__ unsigned packh2(float a, float b) {
    __half2 h = __floats2half2_rn(a, b);
    return *(unsigned*)&h;
}
__device__ __forceinline__ float ex2a(float x) {
    float y;
    asm("ex2.approx.f32 %0, %1;" : "=f"(y) : "f"(x));
    return y;
}

// ---------------------------------------------------------------------------
// Fused prep kernel: one launch covering three independent jobs,
// dispatched on blockIdx.x (all 256-thread blocks):
//   [0, LNB)            warp-per-row LayerNorm (x and context)
//   [LNB, LNB+WTB)      weight transpose + fp16 convert (4 weights)
//   [LNB+WTB, ...+MKB)  mask -> float multiplier (dtype self-detected)
// ---------------------------------------------------------------------------
#define LNB (BATCH * (LQQ + LKK) / 8)          // 2048
#define WTB ((DMODEL / 32) * (DMODEL / 32) * 4) // 4096
#define MKB ((BATCH * LKK) / 256)               // 32

__global__ void prep_kernel(
        const float* __restrict__ x,
        const float* __restrict__ ctx,
        const float* __restrict__ wq_, const float* __restrict__ bq_,
        const float* __restrict__ wc_, const float* __restrict__ bc_,
        __half* __restrict__ oq_, __half* __restrict__ oc_,
        const float* __restrict__ W0, __half* __restrict__ T0,
        const float* __restrict__ W1, __half* __restrict__ T1,
        const float* __restrict__ W2, __half* __restrict__ T2,
        const float* __restrict__ W3, __half* __restrict__ T3,
        const void* __restrict__ m) {
    int bx = blockIdx.x;
    if (bx < LNB) {
        // ---- LayerNorm: one 1024-float row per warp ----
        int wid = threadIdx.x >> 5, lane = threadIdx.x & 31;
        int row = bx * 8 + wid;
        bool isq = row < BATCH * LQQ;
        const float* src = isq ? x : ctx;
        const float* w   = isq ? wq_ : wc_;
        const float* bia = isq ? bq_ : bc_;
        __half* out      = isq ? oq_ : oc_;
        int r = isq ? row : row - BATCH * LQQ;

        const float4* xr = reinterpret_cast<const float4*>(src + (size_t)r * DMODEL);
        float4 xv[8];
        float s = 0.f, ss = 0.f;
        #pragma unroll
        for (int j = 0; j < 8; j++) {
            float4 a = xr[lane + j * 32];
            xv[j] = a;
            s  += a.x + a.y + a.z + a.w;
            ss += a.x * a.x + a.y * a.y + a.z * a.z + a.w * a.w;
        }
        #pragma unroll
        for (int o = 16; o; o >>= 1) {
            s  += __shfl_xor_sync(0xffffffffu, s,  o);
            ss += __shfl_xor_sync(0xffffffffu, ss, o);
        }
        float mean = s * (1.0f / DMODEL);
        float var  = ss * (1.0f / DMODEL) - mean * mean;
        float rstd = rsqrtf(var + 1e-5f);

        const float4* w4 = reinterpret_cast<const float4*>(w);
        const float4* b4 = reinterpret_cast<const float4*>(bia);
        __half* orow = out + (size_t)r * DMODEL;
        #pragma unroll
        for (int j = 0; j < 8; j++) {
            float4 wv = w4[lane + j * 32];
            float4 bv = b4[lane + j * 32];
            float4 a = xv[j];
            __half2 h0 = __floats2half2_rn((a.x - mean) * rstd * wv.x + bv.x,
                                           (a.y - mean) * rstd * wv.y + bv.y);
            __half2 h1 = __floats2half2_rn((a.z - mean) * rstd * wv.z + bv.z,
                                           (a.w - mean) * rstd * wv.w + bv.w);
            uint2 pk = make_uint2(*(unsigned*)&h0, *(unsigned*)&h1);
            *(uint2*)&orow[(lane + j * 32) * 4] = pk;
        }
    } else if (bx < LNB + WTB) {
        // ---- Weight transpose + fp16 ----
        int id = bx - LNB;
        int z  = id >> 10;                 // 4 weights x 1024 tiles
        int t2 = id & 1023;
        int n0 = (t2 & 31) * 32, k0 = (t2 >> 5) * 32;
        const float* W = (z == 0) ? W0 : (z == 1) ? W1 : (z == 2) ? W2 : W3;
        __half* WT     = (z == 0) ? T0 : (z == 1) ? T1 : (z == 2) ? T2 : T3;
        __shared__ float t[32][33];
        int tx = threadIdx.x & 31, ty = threadIdx.x >> 5;
        #pragma unroll
        for (int i = 0; i < 4; i++) {
            int k = ty + i * 8;
            t[k][tx] = W[(size_t)(k0 + k) * DMODEL + n0 + tx];
        }
        __syncthreads();
        #pragma unroll
        for (int i = 0; i < 4; i++) {
            int n = ty + i * 8;
            WT[(size_t)(n0 + n) * DMODEL + k0 + tx] = __float2half(t[tx][n]);
        }
    } else {
        // ---- Mask conversion with per-block dtype self-detection ----
        __shared__ int nz[4];
        if (threadIdx.x < 4) nz[threadIdx.x] = 0;
        __syncthreads();
        const unsigned char* m8 = (const unsigned char*)m;
        int loc[4] = {0, 0, 0, 0};
        for (int i = threadIdx.x; i < 8192; i += blockDim.x)
            if (m8[i]) loc[i & 3] = 1;
        if (loc[0] | loc[1] | loc[2] | loc[3]) {
            if (loc[0]) atomicOr(&nz[0], 1);
            if (loc[1]) atomicOr(&nz[1], 1);
            if (loc[2]) atomicOr(&nz[2], 1);
            if (loc[3]) atomicOr(&nz[3], 1);
        }
        __syncthreads();
        int mode;
        int tot = nz[0] | nz[1] | nz[2] | nz[3];
        if (!tot)                          mode = 0;
        else if (!(nz[1] | nz[2] | nz[3])) mode = 1; // int32 LE
        else if (!(nz[0] | nz[1]))         mode = 2; // float32
        else                               mode = 0; // uint8/bool
        int i = (bx - LNB - WTB) * 256 + threadIdx.x;
        if (i < BATCH * LKK) {
            bool mm = (mode == 0) ? (m8[i] != 0)
                    : (mode == 1) ? (((const int*)m)[i] != 0)
                                  : (((const float*)m)[i] != 0.f);
            g_maskf[i] = mm ? 0.f : 1.f;
        }
    }
}

// ---------------------------------------------------------------------------
// fp16 tensor-core GEMM core, cp.async 3-stage pipeline, ldmatrix loads.
// mode: 0 = half out, 1 = half transposed-per-head out (g_vt, smem-staged),
//       2 = float out, 3 = half out with per-64-col-head L2 normalization.
// ---------------------------------------------------------------------------
#define TBM 128
#define TBN 128
#define TBK 32
#define KPAD 40
#define ROWB (KPAD * 2)
#define ASZH (TBM * KPAD)
#define STAGEB (ASZH * 2)

__device__ __forceinline__ void gemm_core(
        const __half* __restrict__ A,
        const __half* __restrict__ BT,
        void* __restrict__ Cout,
        int M, int N, int K, int mode, __half* gsm) {
    __half* As = gsm;
    __half* Bs = gsm + 3 * ASZH;

    int tid = threadIdx.x;
    int wid = tid >> 5, lane = tid & 31;
    int wm = wid >> 2, wn = wid & 3;
    int m0 = blockIdx.y * TBM, n0 = blockIdx.x * TBN;
    int tg = lane & 3;
    int lm = lane >> 3;
    int lr = lane & 7;

    float acc[4][4][4];
    #pragma unroll
    for (int i = 0; i < 4; i++)
        #pragma unroll
        for (int j = 0; j < 4; j++)
            #pragma unroll
            for (int t = 0; t < 4; t++) acc[i][j][t] = 0.f;

    auto load_tile = [&](int kt, int buf) {
        int k0 = kt * TBK;
        #pragma unroll
        for (int i = 0; i < 2; i++) {
            int cid = tid + i * 256;
            int row = cid >> 2, c8 = (cid & 3) * 8;
            cp_async16(&As[buf * ASZH + row * KPAD + c8],
                       A + (size_t)(m0 + row) * K + k0 + c8);
            cp_async16(&Bs[buf * ASZH + row * KPAD + c8],
                       BT + (size_t)(n0 + row) * K + k0 + c8);
        }
        cp_commit();
    };

    unsigned aoff = (unsigned)((wm * 64 + (lm & 1) * 8 + lr) * ROWB + (lm >> 1) * 16);
    unsigned boff = (unsigned)((wn * 32 + (lm >> 1) * 8 + lr) * ROWB + (lm & 1) * 16);

    unsigned aBase = smem_u32(As) + aoff;
    unsigned bBase = smem_u32(Bs) + boff;

    int nt = K / TBK;
    load_tile(0, 0);
    load_tile(1, 1);

    for (int kt = 0; kt < nt; kt++) {
        int cur = kt % 3;
        if (kt + 2 < nt) cp_wait<1>(); else cp_wait<0>();
        __syncthreads();
        if (kt + 2 < nt) load_tile(kt + 2, (kt + 2) % 3);

        unsigned aS = aBase + cur * STAGEB;
        unsigned bS = bBase + cur * STAGEB;

        #pragma unroll
        for (int ks = 0; ks < 2; ks++) {
            unsigned kofs = ks * 32;
            unsigned af[4][4];
            #pragma unroll
            for (int mf = 0; mf < 4; mf++)
                ldsm4(af[mf][0], af[mf][1], af[mf][2], af[mf][3],
                      aS + kofs + mf * 16 * ROWB);
            unsigned bf[4][2];
            #pragma unroll
            for (int g = 0; g < 2; g++)
                ldsm4(bf[g*2][0], bf[g*2][1], bf[g*2+1][0], bf[g*2+1][1],
                      bS + kofs + g * 16 * ROWB);
            #pragma unroll
            for (int mf = 0; mf < 4; mf++)
                #pragma unroll
                for (int nf = 0; nf < 4; nf++)
                    mma_f16(acc[mf][nf], af[mf][0], af[mf][1], af[mf][2], af[mf][3],
                            bf[nf][0], bf[nf][1]);
        }
    }

    if (mode == 1) {
        __syncthreads();
        __half* ts = gsm;
        int rl = wm * 64 + (lane >> 2);
        int sc = wn * 32 + tg * 2;
        #pragma unroll
        for (int mf = 0; mf < 4; mf++) {
            #pragma unroll
            for (int nf = 0; nf < 4; nf++) {
                int r = rl + mf * 16;
                int c = sc + nf * 8;
                ts[c * 136 + r]           = __float2half(acc[mf][nf][0]);
                ts[(c + 1) * 136 + r]     = __float2half(acc[mf][nf][1]);
                ts[c * 136 + r + 8]       = __float2half(acc[mf][nf][2]);
                ts[(c + 1) * 136 + r + 8] = __float2half(acc[mf][nf][3]);
            }
        }
        __syncthreads();
        __half* vt = (__half*)Cout;
        int bb = m0 >> 11, kv0 = m0 & 2047;
        #pragma unroll
        for (int i = 0; i < 8; i++) {
            int id = tid + i * 256;
            int c = id >> 4, kv8 = (id & 15) * 8;
            *(uint4*)&vt[((size_t)(bb * 1024 + n0 + c)) * 2048 + kv0 + kv8] =
                *(const uint4*)&ts[c * 136 + kv8];
        }
        return;
    }

    float scl[4][2];
    if (mode == 3) {
        float ssql[4][2];
        #pragma unroll
        for (int mf = 0; mf < 4; mf++) {
            float s0 = 0.f, s1 = 0.f;
            #pragma unroll
            for (int nf = 0; nf < 4; nf++) {
                s0 += acc[mf][nf][0] * acc[mf][nf][0] + acc[mf][nf][1] * acc[mf][nf][1];
                s1 += acc[mf][nf][2] * acc[mf][nf][2] + acc[mf][nf][3] * acc[mf][nf][3];
            }
            ssql[mf][0] = s0; ssql[mf][1] = s1;
        }
        #pragma unroll
        for (int mf = 0; mf < 4; mf++) {
            #pragma unroll
            for (int o = 1; o <= 2; o <<= 1) {
                ssql[mf][0] += __shfl_xor_sync(0xffffffffu, ssql[mf][0], o);
                ssql[mf][1] += __shfl_xor_sync(0xffffffffu, ssql[mf][1], o);
            }
        }
        __syncthreads();
        float* ssqs = (float*)gsm;
        int rl = wm * 64 + (lane >> 2);
        if (tg == 0) {
            #pragma unroll
            for (int mf = 0; mf < 4; mf++) {
                ssqs[(rl + mf * 16) * 4 + wn]     = ssql[mf][0];
                ssqs[(rl + mf * 16 + 8) * 4 + wn] = ssql[mf][1];
            }
        }
        __syncthreads();
        int hb = (wn >> 1) * 2;
        #pragma unroll
        for (int mf = 0; mf < 4; mf++) {
            float t0 = ssqs[(rl + mf * 16) * 4 + hb]     + ssqs[(rl + mf * 16) * 4 + hb + 1];
            float t1 = ssqs[(rl + mf * 16 + 8) * 4 + hb] + ssqs[(rl + mf * 16 + 8) * 4 + hb + 1];
            scl[mf][0] = rsqrtf(fmaxf(t0, 1e-24f));
            scl[mf][1] = rsqrtf(fmaxf(t1, 1e-24f));
        }
    }

    int crow = m0 + wm * 64 + (lane >> 2);
    int ccol = n0 + wn * 32 + tg * 2;
    #pragma unroll
    for (int mf = 0; mf < 4; mf++) {
        #pragma unroll
        for (int nf = 0; nf < 4; nf++) {
            int r = crow + mf * 16;
            int c = ccol + nf * 8;
            float v0 = acc[mf][nf][0], v1 = acc[mf][nf][1];
            float v2 = acc[mf][nf][2], v3 = acc[mf][nf][3];
            if (mode == 2) {
                float* Cf = (float*)Cout;
                *(float2*)&Cf[(size_t)r * N + c]       = make_float2(v0, v1);
                *(float2*)&Cf[(size_t)(r + 8) * N + c] = make_float2(v2, v3);
            } else {
                if (mode == 3) {
                    v0 *= scl[mf][0]; v1 *= scl[mf][0];
                    v2 *= scl[mf][1]; v3 *= scl[mf][1];
                }
                __half* Ch = (__half*)Cout;
                *(__half2*)&Ch[(size_t)r * N + c]       = __floats2half2_rn(v0, v1);
                *(__half2*)&Ch[(size_t)(r + 8) * N + c] = __floats2half2_rn(v2, v3);
            }
        }
    }
}

__global__ __launch_bounds__(256, 2) void tgemm_kernel(
        const __half* __restrict__ A,
        const __half* __restrict__ BT,
        void* __restrict__ Cout,
        int M, int N, int K, int mode) {
    extern __shared__ __half gsm[];
    gemm_core(A, BT, Cout, M, N, K, mode, gsm);
}

__global__ __launch_bounds__(256, 2) void qkv3_kernel(
        const __half* __restrict__ qln,
        const __half* __restrict__ kvln,
        const __half* __restrict__ wq,
        const __half* __restrict__ wk,
        const __half* __restrict__ wv,
        __half* __restrict__ q,
        __half* __restrict__ k,
        __half* __restrict__ vt) {
    extern __shared__ __half gsm[];
    int z = blockIdx.z;
    const __half* A  = (z == 0) ? qln : kvln;
    const __half* BT = (z == 0) ? wq : (z == 1) ? wk : wv;
    void* C          = (z == 0) ? (void*)q : (z == 1) ? (void*)k : (void*)vt;
    int mode         = (z == 2) ? 1 : 3;   // q,k: fused per-head l2norm
    gemm_core(A, BT, C, BATCH * LQQ, DMODEL, DMODEL, mode, gsm);
}

// ---------------------------------------------------------------------------
// Flash attention, fp16 mma + ldmatrix, fixed-max softmax via ex2.approx.
// 8 warps split on m only: warp tile 32 q-rows x 64 kv-cols.
// 128-key cp.async stages, two 64-key passes per barrier.
// ---------------------------------------------------------------------------
#define QROWS 256
#define QP 72
#define QROWB (QP * 2)
#define VP 136
#define VROWB (VP * 2)
#define KSTAGE (128 * QP * 2)
#define VSTAGE (64 * VP * 2)

__global__ __launch_bounds__(256) void attn_kernel(
        const __half* __restrict__ Q,
        const __half* __restrict__ Kp,
        const __half* __restrict__ Vt,
        const float* __restrict__ maskf,
        const float* __restrict__ tau_p,
        __half* __restrict__ O) {
    extern __shared__ __half smh[];
    __half* Qs = smh;                    // QROWS*QP
    __half* Ks = Qs + QROWS * QP;        // 2 * 128*QP
    __half* Vs = Ks + 2 * 128 * QP;      // 2 * 64*VP
    float*  Ms = (float*)(Vs + 2 * 64 * VP);  // 2 * 128

    int tid  = threadIdx.x;
    int wid  = tid >> 5, lane = tid & 31;
    int q0   = blockIdx.x * QROWS;
    int h    = blockIdx.y;
    int b    = blockIdx.z;
    int tg   = lane & 3;
    int lm   = lane >> 3;
    int lr   = lane & 7;

    float inv_tau = 1.0f / (*tau_p + 1e-6f);
    const float L2E = 1.44269504f;
    float c1 = inv_tau * L2E;
    float c2 = -fabsf(inv_tau) * L2E;

    const __half* Qbase = Q  + ((size_t)(b * LQQ + q0)) * DMODEL + h * DHEAD;
    const __half* Kbase = Kp + ((size_t)b * LKK) * DMODEL + h * DHEAD;
    const __half* Vbase = Vt + ((size_t)(b * 1024 + h * DHEAD)) * 2048;
    const float*  Mbase = maskf + (size_t)b * LKK;

    #pragma unroll
    for (int i = 0; i < 8; i++) {
        int cid = tid + i * 256;
        int r = cid >> 3, c8 = (cid & 7) * 8;
        cp_async16(&Qs[r * QP + c8], Qbase + (size_t)r * DMODEL + c8);
    }
    cp_commit();

    auto load_kv = [&](int k0, int buf) {
        #pragma unroll
        for (int i = 0; i < 4; i++) {
            int cid = tid + i * 256;
            int rk = cid >> 3, ck = (cid & 7) * 8;
            cp_async16(&Ks[buf * 128 * QP + rk * QP + ck],
                       Kbase + (size_t)(k0 + rk) * DMODEL + ck);
            int rv = cid >> 4, cv = (cid & 15) * 8;
            cp_async16(&Vs[buf * 64 * VP + rv * VP + cv],
                       Vbase + (size_t)rv * 2048 + k0 + cv);
        }
        if (tid < 32) cp_async16(&Ms[buf * 128 + tid * 4], Mbase + k0 + tid * 4);
        cp_commit();
    };

    load_kv(0, 0);

    float oacc[2][8][4];
    #pragma unroll
    for (int m = 0; m < 2; m++)
        #pragma unroll
        for (int i = 0; i < 8; i++)
            #pragma unroll
            for (int j = 0; j < 4; j++) oacc[m][i][j] = 0.f;
    float lsum[2][2] = {};

    unsigned aoff  = (unsigned)((wid * 32 + (lm & 1) * 8 + lr) * QROWB + (lm >> 1) * 16);
    unsigned boffK = (unsigned)(((lm >> 1) * 8 + lr) * QROWB + (lm & 1) * 16);
    unsigned boffV = (unsigned)(((lm >> 1) * 8 + lr) * VROWB + (lm & 1) * 16);
    unsigned qA = smem_u32(Qs) + aoff;
    unsigned kB = smem_u32(Ks) + boffK;
    unsigned vB = smem_u32(Vs) + boffV;

    const int NT = LKK / 128;
    for (int kt = 0; kt < NT; kt++) {
        int cur = kt & 1;
        cp_wait<0>();
        __syncthreads();
        if (kt + 1 < NT) load_kv((kt + 1) * 128, cur ^ 1);

        #pragma unroll
        for (int p = 0; p < 2; p++) {
            unsigned kS = kB + cur * KSTAGE + p * 64 * QROWB;
            unsigned vS = vB + cur * VSTAGE + p * 128;
            const float* Msb = Ms + cur * 128 + p * 64;

            float sacc[2][8][4];
            #pragma unroll
            for (int m = 0; m < 2; m++)
                #pragma unroll
                for (int i = 0; i < 8; i++)
                    #pragma unroll
                    for (int j = 0; j < 4; j++) sacc[m][i][j] = 0.f;

            #pragma unroll
            for (int ks = 0; ks < 4; ks++) {
                unsigned kofs = ks * 32;
                unsigned bf[8][2];
                #pragma unroll
                for (int g = 0; g < 4; g++)
                    ldsm4(bf[g*2][0], bf[g*2][1], bf[g*2+1][0], bf[g*2+1][1],
                          kS + kofs + g * 16 * QROWB);
                #pragma unroll
                for (int mf = 0; mf < 2; mf++) {
                    unsigned a0, a1, a2, a3;
                    ldsm4(a0, a1, a2, a3, qA + kofs + mf * 16 * QROWB);
                    #pragma unroll
                    for (int nf = 0; nf < 8; nf++)
                        mma_f16(sacc[mf][nf], a0, a1, a2, a3, bf[nf][0], bf[nf][1]);
                }
            }

            float2 mk2[8];
            #pragma unroll
            for (int nf = 0; nf < 8; nf++)
                mk2[nf] = *(const float2*)&Msb[nf * 8 + tg * 2];

            unsigned ph[2][8][2];
            #pragma unroll
            for (int mf = 0; mf < 2; mf++) {
                #pragma unroll
                for (int nf = 0; nf < 8; nf++) {
                    float p00 = ex2a(fmaf(sacc[mf][nf][0], c1, c2)) * mk2[nf].x;
                    float p01 = ex2a(fmaf(sacc[mf][nf][1], c1, c2)) * mk2[nf].y;
                    float p10 = ex2a(fmaf(sacc[mf][nf][2], c1, c2)) * mk2[nf].x;
                    float p11 = ex2a(fmaf(sacc[mf][nf][3], c1, c2)) * mk2[nf].y;
                    lsum[mf][0] += p00 + p01;
                    lsum[mf][1] += p10 + p11;
                    ph[mf][nf][0] = packh2(p00, p01);
                    ph[mf][nf][1] = packh2(p10, p11);
                }
            }

            #pragma unroll
            for (int ks = 0; ks < 4; ks++) {
                unsigned kofs = ks * 32;
                unsigned bf[8][2];
                #pragma unroll
                for (int g = 0; g < 4; g++)
                    ldsm4(bf[g*2][0], bf[g*2][1], bf[g*2+1][0], bf[g*2+1][1],
                          vS + kofs + g * 16 * VROWB);
                #pragma unroll
                for (int mf = 0; mf < 2; mf++) {
                    unsigned a0 = ph[mf][2*ks][0];
                    unsigned a1 = ph[mf][2*ks][1];
                    unsigned a2 = ph[mf][2*ks+1][0];
                    unsigned a3 = ph[mf][2*ks+1][1];
                    #pragma unroll
                    for (int nf = 0; nf < 8; nf++)
                        mma_f16(oacc[mf][nf], a0, a1, a2, a3, bf[nf][0], bf[nf][1]);
                }
            }
        }
    }

    #pragma unroll
    for (int mf = 0; mf < 2; mf++) {
        lsum[mf][0] += __shfl_xor_sync(0xffffffffu, lsum[mf][0], 1);
        lsum[mf][0] += __shfl_xor_sync(0xffffffffu, lsum[mf][0], 2);
        lsum[mf][1] += __shfl_xor_sync(0xffffffffu, lsum[mf][1], 1);
        lsum[mf][1] += __shfl_xor_sync(0xffffffffu, lsum[mf][1], 2);
    }

    int rA = wid * 32 + (lane >> 2);
    #pragma unroll
    for (int mf = 0; mf < 2; mf++) {
        int r0 = rA + mf * 16;
        float li0 = 1.0f / lsum[mf][0];
        float li1 = 1.0f / lsum[mf][1];
        int gcol = h * DHEAD + tg * 2;
        #pragma unroll
        for (int nf = 0; nf < 8; nf++) {
            size_t base0 = ((size_t)(b * LQQ + q0 + r0)) * DMODEL + gcol + nf * 8;
            size_t base1 = ((size_t)(b * LQQ + q0 + r0 + 8)) * DMODEL + gcol + nf * 8;
            *(__half2*)&O[base0] = __floats2half2_rn(oacc[mf][nf][0] * li0,
                                                     oacc[mf][nf][1] * li0);
            *(__half2*)&O[base1] = __floats2half2_rn(oacc[mf][nf][2] * li1,
                                                     oacc[mf][nf][3] * li1);
        }
    }
}

// ---------------------------------------------------------------------------
// Launcher
// ---------------------------------------------------------------------------
extern "C" void kernel_launch(void* const* d_in, const int* in_sizes, int n_in,
                              void* d_out, int out_size) {
    const float* x     = (const float*)d_in[0];
    const float* ctx   = (const float*)d_in[1];
    const void*  mask  = d_in[2];
    const float* lnqw  = (const float*)d_in[3];
    const float* lnqb  = (const float*)d_in[4];
    const float* lncw  = (const float*)d_in[5];
    const float* lncb  = (const float*)d_in[6];
    const float* Wq    = (const float*)d_in[7];
    const float* Wk    = (const float*)d_in[8];
    const float* Wv    = (const float*)d_in[9];
    const float* Wo    = (const float*)d_in[10];
    const float* taup  = (const float*)d_in[11];
    float* out = (float*)d_out;

    __half *qln, *kvln, *q, *k, *vt, *ao, *wq, *wk, *wv, *wo;
    float *maskf;
    cudaGetSymbolAddress((void**)&qln,   g_qln);
    cudaGetSymbolAddress((void**)&kvln,  g_kvln);
    cudaGetSymbolAddress((void**)&q,     g_q);
    cudaGetSymbolAddress((void**)&k,     g_k);
    cudaGetSymbolAddress((void**)&vt,    g_vt);
    cudaGetSymbolAddress((void**)&ao,    g_ao);
    cudaGetSymbolAddress((void**)&maskf, g_maskf);
    cudaGetSymbolAddress((void**)&wq,    g_wq);
    cudaGetSymbolAddress((void**)&wk,    g_wk);
    cudaGetSymbolAddress((void**)&wv,    g_wv);
    cudaGetSymbolAddress((void**)&wo,    g_wo);

    const int smem_gemm = (int)(6 * ASZH * sizeof(__half));
    cudaFuncSetAttribute(tgemm_kernel, cudaFuncAttributeMaxDynamicSharedMemorySize, smem_gemm);
    cudaFuncSetAttribute(qkv3_kernel,  cudaFuncAttributeMaxDynamicSharedMemorySize, smem_gemm);

    const int smem_attn = (int)((QROWS * QP + 2 * 128 * QP + 2 * 64 * VP) * sizeof(__half)
                              + 2 * 128 * sizeof(float));
    cudaFuncSetAttribute(attn_kernel, cudaFuncAttributeMaxDynamicSharedMemorySize, smem_attn);

    // one fused prep launch: LN + weight transpose + mask conversion
    prep_kernel<<<LNB + WTB + MKB, 256>>>(
        x, ctx, lnqw, lnqb, lncw, lncb, qln, kvln,
        Wq, wq, Wk, wk, Wv, wv, Wo, wo, mask);

    // fused Q/K/V projections; q,k l2-normalized in the epilogue (mode 3)
    dim3 gqkv(DMODEL / TBN, (BATCH * LQQ) / TBM, 3);
    qkv3_kernel<<<gqkv, 256, smem_gemm>>>(qln, kvln, wq, wk, wv, q, k, vt);

    attn_kernel<<<dim3(LQQ / QROWS, NHEAD, BATCH), 256, smem_attn>>>(q, k, vt, maskf, taup, ao);

    dim3 gg(DMODEL / TBN, (BATCH * LQQ) / TBM);
    tgemm_kernel<<<gg, 256, smem_gemm>>>(ao, wo, out, BATCH * LQQ, DMODEL, DMODEL, 2);
}